// round 2
// baseline (speedup 1.0000x reference)
#include <cuda_runtime.h>
#include <cstdint>

#define NNODES 100000
#define D 128
#define EMAX 2000000
#define BN_EPS 1e-5f

// ---------------- device scratch (no dynamic allocation allowed) ----------------
__device__ float g_h[(size_t)NNODES * D];     // h = x @ W^T   (51.2 MB, L2-resident)
__device__ float g_dinv[NNODES];              // 1/sqrt(deg)
__device__ int   g_counts[NNODES];            // in-degree (excluding self loop)
__device__ int   g_rowstart[NNODES];          // CSR row offsets (exclusive scan)
__device__ int   g_cursor[NNODES];            // fill cursors
__device__ int   g_csr[EMAX];                 // CSR column (src) indices
__device__ int   g_blocksums[128];            // scan partials
__device__ float g_stats[2 * D];              // [0..127] sum, [128..255] sumsq
__device__ int   g_is64;                      // edge_index dtype flag

// ---------------- edge index access (dtype detected at runtime) ----------------
__device__ __forceinline__ int edge_at(const void* ei, long long pos) {
    if (g_is64) return (int)((const long long*)ei)[pos];
    return ((const int*)ei)[pos];
}

// int64 little-endian => odd int32 words of first pairs are all zero
// (indices are < 2^31 and nonnegative).
__global__ void k_detect(const int* ei32, int E) {
    int all0 = 1;
    int lim = (E < 64) ? E : 64;
    for (int k = 0; k < lim; k++)
        if (ei32[2 * k + 1] != 0) { all0 = 0; break; }
    g_is64 = all0;
}

__global__ void k_init(int N) {
    int i = blockIdx.x * blockDim.x + threadIdx.x;
    if (i < N) g_counts[i] = 0;
    if (i < 2 * D) g_stats[i] = 0.0f;
}

__global__ void k_hist(const void* ei, int E) {
    int e = blockIdx.x * blockDim.x + threadIdx.x;
    if (e >= E) return;
    int d = edge_at(ei, (long long)E + e);
    atomicAdd(&g_counts[d], 1);
}

// ---- 3-kernel exclusive scan over g_counts -> g_rowstart ----
__global__ void k_scan1(int N) {
    __shared__ int sh[1024];
    int t = threadIdx.x;
    int gid = blockIdx.x * 1024 + t;
    int v = (gid < N) ? g_counts[gid] : 0;
    sh[t] = v;
    __syncthreads();
    for (int off = 1; off < 1024; off <<= 1) {
        int add = (t >= off) ? sh[t - off] : 0;
        __syncthreads();
        sh[t] += add;
        __syncthreads();
    }
    if (gid < N) g_rowstart[gid] = sh[t] - v;   // exclusive
    if (t == 1023) g_blocksums[blockIdx.x] = sh[1023];
}

__global__ void k_scan2(int nblk) {
    __shared__ int sh[128];
    int t = threadIdx.x;
    int v = (t < nblk) ? g_blocksums[t] : 0;
    sh[t] = v;
    __syncthreads();
    for (int off = 1; off < 128; off <<= 1) {
        int add = (t >= off) ? sh[t - off] : 0;
        __syncthreads();
        sh[t] += add;
        __syncthreads();
    }
    if (t < nblk) g_blocksums[t] = sh[t] - v;   // exclusive
}

__global__ void k_scan3(int N) {
    int i = blockIdx.x * blockDim.x + threadIdx.x;
    if (i >= N) return;
    int rs = g_rowstart[i] + g_blocksums[i >> 10];
    g_rowstart[i] = rs;
    g_cursor[i]   = rs;
    g_dinv[i]     = rsqrtf((float)g_counts[i] + 1.0f);  // +1 self loop
}

__global__ void k_fill(const void* ei, int E) {
    int e = blockIdx.x * blockDim.x + threadIdx.x;
    if (e >= E) return;
    int s = edge_at(ei, e);
    int d = edge_at(ei, (long long)E + e);
    int pos = atomicAdd(&g_cursor[d], 1);
    if (pos < EMAX) g_csr[pos] = s;
}

// ---------------- GEMM: h = x @ W^T (fp32, 128x128 tile, 8x8 microtile) ----------
__global__ __launch_bounds__(256) void k_gemm(const float* __restrict__ x,
                                              const float* __restrict__ W, int N) {
    extern __shared__ float4 smem[];
    float4* xs4 = smem;          // 128 rows x 32 float4, XOR-swizzled
    float4* ws4 = smem + 4096;   // 128 rows x 32 float4, XOR-swizzled
    int tid = threadIdx.x;
    int row0 = blockIdx.x * 128;

    const float4* W4 = (const float4*)W;
    for (int i = tid; i < 4096; i += 256) {
        int r = i >> 5, k4 = i & 31;
        ws4[r * 32 + (k4 ^ ((r >> 3) & 7))] = W4[i];
    }
    const float4* x4 = (const float4*)x;
    for (int i = tid; i < 4096; i += 256) {
        int r = i >> 5, k4 = i & 31;
        int gr = row0 + r;
        float4 v = make_float4(0.f, 0.f, 0.f, 0.f);
        if (gr < N) v = x4[(size_t)gr * 32 + k4];
        xs4[r * 32 + (k4 ^ ((r >> 3) & 7))] = v;
    }
    __syncthreads();

    int warp = tid >> 5, lane = tid & 31;
    int warp_m = warp & 3, warp_n = warp >> 2;     // 4 x 2 warps
    int lane_m = lane >> 3, lane_n = lane & 7;     // 4 x 8 lanes
    int r0 = warp_m * 32 + lane_m * 8;
    int c0 = warp_n * 64 + lane_n * 8;
    int sa = (r0 >> 3) & 7, sb = (c0 >> 3) & 7;

    float acc[8][8];
#pragma unroll
    for (int i = 0; i < 8; i++)
#pragma unroll
        for (int j = 0; j < 8; j++) acc[i][j] = 0.f;

#pragma unroll 4
    for (int k4 = 0; k4 < 32; k4++) {
        float4 a[8], bb[8];
#pragma unroll
        for (int i = 0; i < 8; i++) a[i]  = xs4[(r0 + i) * 32 + (k4 ^ sa)];
#pragma unroll
        for (int j = 0; j < 8; j++) bb[j] = ws4[(c0 + j) * 32 + (k4 ^ sb)];
#pragma unroll
        for (int i = 0; i < 8; i++)
#pragma unroll
            for (int j = 0; j < 8; j++) {
                acc[i][j] += a[i].x * bb[j].x;
                acc[i][j] += a[i].y * bb[j].y;
                acc[i][j] += a[i].z * bb[j].z;
                acc[i][j] += a[i].w * bb[j].w;
            }
    }

#pragma unroll
    for (int i = 0; i < 8; i++) {
        int gr = row0 + r0 + i;
        if (gr < N) {
            float4 o0 = make_float4(acc[i][0], acc[i][1], acc[i][2], acc[i][3]);
            float4 o1 = make_float4(acc[i][4], acc[i][5], acc[i][6], acc[i][7]);
            float4* hp = (float4*)&g_h[(size_t)gr * D + c0];
            hp[0] = o0;
            hp[1] = o1;
        }
    }
}

// ---------------- aggregation: warp per node, CSR gather-sum (no float atomics) --
__global__ void k_agg(const float* __restrict__ bias, float* __restrict__ out, int N) {
    int warp = (blockIdx.x * blockDim.x + threadIdx.x) >> 5;
    int lane = threadIdx.x & 31;
    if (warp >= N) return;
    int   base = g_rowstart[warp];
    int   cnt  = g_counts[warp];
    float di   = g_dinv[warp];
    const float4* h4 = (const float4*)g_h;

    float4 self = h4[(size_t)warp * 32 + lane];
    float4 acc  = make_float4(0.f, 0.f, 0.f, 0.f);

    for (int j0 = 0; j0 < cnt; j0 += 32) {
        int myj = j0 + lane;
        int   s   = 0;
        float mns = 0.f;
        if (myj < cnt) {
            s   = g_csr[base + myj];
            mns = g_dinv[s];
        }
        int m = min(32, cnt - j0);
        for (int t = 0; t < m; t++) {
            int   sv = __shfl_sync(0xffffffffu, s, t);
            float ns = __shfl_sync(0xffffffffu, mns, t);
            float4 hv = h4[(size_t)sv * 32 + lane];
            acc.x += ns * hv.x;
            acc.y += ns * hv.y;
            acc.z += ns * hv.z;
            acc.w += ns * hv.w;
        }
    }
    float sn = di * di;
    float4 bb = ((const float4*)bias)[lane];
    float4 o;
    o.x = di * acc.x + sn * self.x + bb.x;
    o.y = di * acc.y + sn * self.y + bb.y;
    o.z = di * acc.z + sn * self.z + bb.z;
    o.w = di * acc.w + sn * self.w + bb.w;
    ((float4*)out)[(size_t)warp * 32 + lane] = o;
}

// ---------------- BN statistics (per-feature sum / sumsq) -----------------------
__global__ void k_stats(const float* __restrict__ out, int N) {
    int col = threadIdx.x & 127;
    int rl  = threadIdx.x >> 7;          // 0 or 1
    float s = 0.f, sq = 0.f;
    for (int r = blockIdx.x * 2 + rl; r < N; r += gridDim.x * 2) {
        float v = out[(size_t)r * D + col];
        s  += v;
        sq += v * v;
    }
    atomicAdd(&g_stats[col], s);
    atomicAdd(&g_stats[D + col], sq);
}

// ---------------- BN + ReLU + residual ------------------------------------------
__global__ void k_final(const float* __restrict__ x, const float* __restrict__ gamma,
                        const float* __restrict__ beta, float* __restrict__ out, int N) {
    long long i = (long long)blockIdx.x * blockDim.x + threadIdx.x; // float4 index
    long long total = (long long)N * 32;
    if (i >= total) return;
    int c4 = (int)(i & 31);
    float invN = 1.0f / (float)N;
    float4 v  = ((float4*)out)[i];
    float4 xv = ((const float4*)x)[i];
    float r[4] = {v.x, v.y, v.z, v.w};
    float xr[4] = {xv.x, xv.y, xv.z, xv.w};
#pragma unroll
    for (int c = 0; c < 4; c++) {
        int col = c4 * 4 + c;
        float mu  = g_stats[col] * invN;
        float var = g_stats[D + col] * invN - mu * mu;
        float inv = rsqrtf(var + BN_EPS);
        float y = __ldg(&gamma[col]) * (r[c] - mu) * inv + __ldg(&beta[col]);
        y = fmaxf(y, 0.0f);
        r[c] = y + xr[c];
    }
    ((float4*)out)[i] = make_float4(r[0], r[1], r[2], r[3]);
}

// ---------------- launcher --------------------------------------------------------
extern "C" void kernel_launch(void* const* d_in, const int* in_sizes, int n_in,
                              void* d_out, int out_size) {
    const float* x     = (const float*)d_in[0];
    const float* W     = (const float*)d_in[1];
    const float* bias  = (const float*)d_in[2];
    const float* gamma = (const float*)d_in[3];
    const float* beta  = (const float*)d_in[4];
    const void*  ei    = d_in[5];
    int N = in_sizes[0] / D;
    int E = in_sizes[5] / 2;
    float* out = (float*)d_out;

    cudaFuncSetAttribute(k_gemm, cudaFuncAttributeMaxDynamicSharedMemorySize, 131072);

    k_detect<<<1, 1>>>((const int*)ei, E);
    k_init<<<(N + 255) / 256, 256>>>(N);
    k_hist<<<(E + 255) / 256, 256>>>(ei, E);
    int nblk = (N + 1023) / 1024;
    k_scan1<<<nblk, 1024>>>(N);
    k_scan2<<<1, 128>>>(nblk);
    k_scan3<<<(N + 255) / 256, 256>>>(N);
    k_fill<<<(E + 255) / 256, 256>>>(ei, E);
    k_gemm<<<(N + 127) / 128, 256, 131072>>>(x, W, N);
    k_agg<<<(int)(((long long)N * 32 + 255) / 256), 256>>>(bias, out, N);
    k_stats<<<512, 256>>>(out, N);
    k_final<<<(int)(((long long)N * 32 + 255) / 256), 256>>>(x, gamma, beta, out, N);
}

// round 4
// speedup vs baseline: 1.3392x; 1.3392x over previous
#include <cuda_runtime.h>
#include <cuda_bf16.h>
#include <cstdint>

#define NNODES 100000
#define D 128
#define EMAX 2000000
#define BN_EPS 1e-5f

// ---------------- device scratch (no dynamic allocation allowed) ----------------
__device__ float g_h[(size_t)NNODES * D];     // h = x @ W^T   (51.2 MB)
__device__ float g_dinv[NNODES];              // 1/sqrt(deg)
__device__ int   g_counts[NNODES];            // in-degree (excluding self loop)
__device__ int   g_rowstart[NNODES];          // CSR row offsets
__device__ int   g_cursor[NNODES];            // fill cursors
__device__ int   g_csr[EMAX];                 // CSR column (src) indices
__device__ int   g_blocksums[128];            // scan partials
__device__ float g_stats[2 * D];              // sums / sumsq
__device__ int   g_is64;                      // edge_index dtype flag
// W split into bf16 hi/lo, stored pre-swizzled (ldmatrix layout), 32KB each
__device__ __align__(16) __nv_bfloat16 g_Whi_img[16384];
__device__ __align__(16) __nv_bfloat16 g_Wlo_img[16384];

// ---------------- warp-mma helpers (plain sm_80+ PTX, no 'a'-gated features) -----
__device__ __forceinline__ uint32_t smem_u32(const void* p) {
    uint32_t a;
    asm("{ .reg .u64 t; cvta.to.shared.u64 t, %1; cvt.u32.u64 %0, t; }" : "=r"(a) : "l"(p));
    return a;
}
__device__ __forceinline__ void ldm_x4(uint32_t& r0, uint32_t& r1, uint32_t& r2, uint32_t& r3,
                                       uint32_t addr) {
    asm volatile("ldmatrix.sync.aligned.m8n8.x4.shared.b16 {%0,%1,%2,%3}, [%4];"
                 : "=r"(r0), "=r"(r1), "=r"(r2), "=r"(r3) : "r"(addr));
}
__device__ __forceinline__ void mma_bf16(float* c, const uint32_t* a, const uint32_t* b) {
    asm volatile(
        "mma.sync.aligned.m16n8k16.row.col.f32.bf16.bf16.f32 "
        "{%0,%1,%2,%3},{%4,%5,%6,%7},{%8,%9},{%0,%1,%2,%3};"
        : "+f"(c[0]), "+f"(c[1]), "+f"(c[2]), "+f"(c[3])
        : "r"(a[0]), "r"(a[1]), "r"(a[2]), "r"(a[3]), "r"(b[0]), "r"(b[1]));
}

// ---------------- edge index access (dtype detected at runtime) ----------------
__device__ __forceinline__ int edge_at(const void* ei, long long pos) {
    if (g_is64) return (int)((const long long*)ei)[pos];
    return ((const int*)ei)[pos];
}

__global__ void k_detect(const int* ei32, int E) {
    int all0 = 1;
    int lim = (E < 64) ? E : 64;
    for (int k = 0; k < lim; k++)
        if (ei32[2 * k + 1] != 0) { all0 = 0; break; }
    g_is64 = all0;
}

__global__ void k_init(int N) {
    int i = blockIdx.x * blockDim.x + threadIdx.x;
    if (i < N) g_counts[i] = 0;
    if (i < 2 * D) g_stats[i] = 0.0f;
}

__global__ void k_hist(const void* ei, int E) {
    int e = blockIdx.x * blockDim.x + threadIdx.x;
    if (e >= E) return;
    int d = edge_at(ei, (long long)E + e);
    atomicAdd(&g_counts[d], 1);
}

// ---- 3-kernel exclusive scan over g_counts -> g_rowstart ----
__global__ void k_scan1(int N) {
    __shared__ int sh[1024];
    int t = threadIdx.x;
    int gid = blockIdx.x * 1024 + t;
    int v = (gid < N) ? g_counts[gid] : 0;
    sh[t] = v;
    __syncthreads();
    for (int off = 1; off < 1024; off <<= 1) {
        int add = (t >= off) ? sh[t - off] : 0;
        __syncthreads();
        sh[t] += add;
        __syncthreads();
    }
    if (gid < N) g_rowstart[gid] = sh[t] - v;
    if (t == 1023) g_blocksums[blockIdx.x] = sh[1023];
}

__global__ void k_scan2(int nblk) {
    __shared__ int sh[128];
    int t = threadIdx.x;
    int v = (t < nblk) ? g_blocksums[t] : 0;
    sh[t] = v;
    __syncthreads();
    for (int off = 1; off < 128; off <<= 1) {
        int add = (t >= off) ? sh[t - off] : 0;
        __syncthreads();
        sh[t] += add;
        __syncthreads();
    }
    if (t < nblk) g_blocksums[t] = sh[t] - v;
}

__global__ void k_scan3(int N) {
    int i = blockIdx.x * blockDim.x + threadIdx.x;
    if (i >= N) return;
    int rs = g_rowstart[i] + g_blocksums[i >> 10];
    g_rowstart[i] = rs;
    g_cursor[i]   = rs;
    g_dinv[i]     = rsqrtf((float)g_counts[i] + 1.0f);
}

__global__ void k_fill(const void* ei, int E) {
    int e = blockIdx.x * blockDim.x + threadIdx.x;
    if (e >= E) return;
    int s = edge_at(ei, e);
    int d = edge_at(ei, (long long)E + e);
    int pos = atomicAdd(&g_cursor[d], 1);
    if (pos < EMAX) g_csr[pos] = s;
}

// ---------------- W split: fp32 -> bf16 hi/lo, ldmatrix-swizzled image -----------
// layout: bf16 index (r*16 + (kc ^ (r&7)))*8 + (k&7),  r=row(n), kc=k>>3
__global__ void k_wsplit(const float* __restrict__ W) {
    int e = blockIdx.x * blockDim.x + threadIdx.x;
    if (e >= 16384) return;
    int r = e >> 7, k = e & 127;
    float w = W[e];
    __nv_bfloat16 hi = __float2bfloat16(w);
    __nv_bfloat16 lo = __float2bfloat16(w - __bfloat162float(hi));
    int kc = k >> 3;
    int idx = (r * 16 + (kc ^ (r & 7))) * 8 + (k & 7);
    g_Whi_img[idx] = hi;
    g_Wlo_img[idx] = lo;
}

// ---------------- GEMM: h = x @ W^T via mma.sync bf16 3-term split --------------
// SMEM: A_hi(32K) A_lo(32K) B_hi(32K) B_lo(32K) = 131072 bytes
#define SM_AHI 0
#define SM_ALO 32768
#define SM_BHI 65536
#define SM_BLO 98304
#define SM_TOT 131072

__global__ __launch_bounds__(256) void k_gemm_mma(const float* __restrict__ x, int N) {
    extern __shared__ char smem[];
    uint32_t sb = smem_u32(smem);
    int tid = threadIdx.x;
    int row0 = blockIdx.x * 128;

    // ---- copy pre-swizzled W hi/lo images (2048 uint4 each) ----
    {
        const uint4* wh = (const uint4*)g_Whi_img;
        const uint4* wl = (const uint4*)g_Wlo_img;
        uint4* bh = (uint4*)(smem + SM_BHI);
        uint4* bl = (uint4*)(smem + SM_BLO);
        for (int i = tid; i < 2048; i += 256) { bh[i] = wh[i]; bl[i] = wl[i]; }
    }

    // ---- convert this tile's x rows to bf16 hi/lo, swizzled ----
    {
        int r  = tid >> 1;          // 0..127
        int hf = tid & 1;           // half-row
        int gr = row0 + r;
        char* Ah = smem + SM_AHI;
        char* Al = smem + SM_ALO;
        if (gr < N) {
            const float4* xr = (const float4*)(x + (size_t)gr * 128) + hf * 16;
#pragma unroll
            for (int j = 0; j < 8; j++) {
                float4 v0 = xr[2 * j];
                float4 v1 = xr[2 * j + 1];
                float f[8] = {v0.x, v0.y, v0.z, v0.w, v1.x, v1.y, v1.z, v1.w};
                uint32_t hw[4], lw[4];
#pragma unroll
                for (int q = 0; q < 4; q++) {
                    float a = f[2 * q], b = f[2 * q + 1];
                    __nv_bfloat16 ha = __float2bfloat16(a);
                    __nv_bfloat16 hb = __float2bfloat16(b);
                    union { __nv_bfloat162 v; uint32_t u; } ch, cl;
                    ch.v = __nv_bfloat162(ha, hb);
                    cl.v = __nv_bfloat162(__float2bfloat16(a - __bfloat162float(ha)),
                                          __float2bfloat16(b - __bfloat162float(hb)));
                    hw[q] = ch.u;
                    lw[q] = cl.u;
                }
                int kc = hf * 8 + j;
                int off = (r * 16 + (kc ^ (r & 7))) * 16;
                *(uint4*)(Ah + off) = make_uint4(hw[0], hw[1], hw[2], hw[3]);
                *(uint4*)(Al + off) = make_uint4(lw[0], lw[1], lw[2], lw[3]);
            }
        } else {
            uint4 z = make_uint4(0, 0, 0, 0);
#pragma unroll
            for (int j = 0; j < 8; j++) {
                int kc = hf * 8 + j;
                int off = (r * 16 + (kc ^ (r & 7))) * 16;
                *(uint4*)(smem + SM_AHI + off) = z;
                *(uint4*)(smem + SM_ALO + off) = z;
            }
        }
    }
    __syncthreads();

    // ---- warp tiles: 8 warps, 4x2 -> warp tile 32(m) x 64(n) ----
    int warp = tid >> 5, lane = tid & 31;
    int wm = warp & 3, wn = warp >> 2;
    int m0 = wm * 32, n0 = wn * 64;
    int sub = lane >> 3, lrow = lane & 7;

    float acc[2][8][4];
#pragma unroll
    for (int mt = 0; mt < 2; mt++)
#pragma unroll
        for (int nt = 0; nt < 8; nt++)
#pragma unroll
            for (int q = 0; q < 4; q++) acc[mt][nt][q] = 0.f;

    // A-lane address pieces: row = m0 + mt*16 + (sub&1)*8 + lrow; halfk = sub>>1
    int a_row_off = ((sub & 1) << 3) + lrow;
    int a_halfk   = sub >> 1;
    // B-lane: row = n0 + np*16 + ((sub&2)?8:0) + lrow; halfk = sub&1
    int b_row_off = ((sub & 2) << 2) + lrow;
    int b_halfk   = sub & 1;

#pragma unroll
    for (int ks = 0; ks < 8; ks++) {
        uint32_t ah[2][4], al[2][4], bh[8][2], bl[8][2];
#pragma unroll
        for (int mt = 0; mt < 2; mt++) {
            int r = m0 + mt * 16 + a_row_off;
            int kc = 2 * ks + a_halfk;
            uint32_t addr = (uint32_t)((r * 16 + (kc ^ (r & 7))) * 16);
            ldm_x4(ah[mt][0], ah[mt][1], ah[mt][2], ah[mt][3], sb + SM_AHI + addr);
            ldm_x4(al[mt][0], al[mt][1], al[mt][2], al[mt][3], sb + SM_ALO + addr);
        }
#pragma unroll
        for (int np = 0; np < 4; np++) {
            int r = n0 + np * 16 + b_row_off;
            int kc = 2 * ks + b_halfk;
            uint32_t addr = (uint32_t)((r * 16 + (kc ^ (r & 7))) * 16);
            ldm_x4(bh[2 * np][0], bh[2 * np][1], bh[2 * np + 1][0], bh[2 * np + 1][1],
                   sb + SM_BHI + addr);
            ldm_x4(bl[2 * np][0], bl[2 * np][1], bl[2 * np + 1][0], bl[2 * np + 1][1],
                   sb + SM_BLO + addr);
        }
#pragma unroll
        for (int mt = 0; mt < 2; mt++)
#pragma unroll
            for (int nt = 0; nt < 8; nt++) {
                mma_bf16(acc[mt][nt], ah[mt], bh[nt]);
                mma_bf16(acc[mt][nt], ah[mt], bl[nt]);
                mma_bf16(acc[mt][nt], al[mt], bh[nt]);
            }
    }

    // ---- epilogue: c frag -> float2 global stores ----
    int qrow = lane >> 2, qcol = (lane & 3) * 2;
#pragma unroll
    for (int mt = 0; mt < 2; mt++) {
        int r_lo = row0 + m0 + mt * 16 + qrow;
        int r_hi = r_lo + 8;
#pragma unroll
        for (int nt = 0; nt < 8; nt++) {
            int col = n0 + nt * 8 + qcol;
            if (r_lo < N)
                *(float2*)&g_h[(size_t)r_lo * D + col] = make_float2(acc[mt][nt][0], acc[mt][nt][1]);
            if (r_hi < N)
                *(float2*)&g_h[(size_t)r_hi * D + col] = make_float2(acc[mt][nt][2], acc[mt][nt][3]);
        }
    }
}

// ---------------- aggregation: warp per node, CSR gather-sum ---------------------
__global__ void k_agg(const float* __restrict__ bias, float* __restrict__ out, int N) {
    int warp = (blockIdx.x * blockDim.x + threadIdx.x) >> 5;
    int lane = threadIdx.x & 31;
    if (warp >= N) return;
    int   base = g_rowstart[warp];
    int   cnt  = g_counts[warp];
    float di   = g_dinv[warp];
    const float4* h4 = (const float4*)g_h;

    float4 self = h4[(size_t)warp * 32 + lane];
    float4 acc  = make_float4(0.f, 0.f, 0.f, 0.f);

    for (int j0 = 0; j0 < cnt; j0 += 32) {
        int myj = j0 + lane;
        int   s   = 0;
        float mns = 0.f;
        if (myj < cnt) {
            s   = g_csr[base + myj];
            mns = g_dinv[s];
        }
        int m = min(32, cnt - j0);
        for (int t = 0; t < m; t++) {
            int   sv = __shfl_sync(0xffffffffu, s, t);
            float ns = __shfl_sync(0xffffffffu, mns, t);
            float4 hv = h4[(size_t)sv * 32 + lane];
            acc.x += ns * hv.x;
            acc.y += ns * hv.y;
            acc.z += ns * hv.z;
            acc.w += ns * hv.w;
        }
    }
    float sn = di * di;
    float4 bb = ((const float4*)bias)[lane];
    float4 o;
    o.x = di * acc.x + sn * self.x + bb.x;
    o.y = di * acc.y + sn * self.y + bb.y;
    o.z = di * acc.z + sn * self.z + bb.z;
    o.w = di * acc.w + sn * self.w + bb.w;
    ((float4*)out)[(size_t)warp * 32 + lane] = o;
}

// ---------------- BN statistics ---------------------------------------------------
__global__ void k_stats(const float* __restrict__ out, int N) {
    int col = threadIdx.x & 127;
    int rl  = threadIdx.x >> 7;
    float s = 0.f, sq = 0.f;
    for (int r = blockIdx.x * 2 + rl; r < N; r += gridDim.x * 2) {
        float v = out[(size_t)r * D + col];
        s  += v;
        sq += v * v;
    }
    atomicAdd(&g_stats[col], s);
    atomicAdd(&g_stats[D + col], sq);
}

// ---------------- BN + ReLU + residual -------------------------------------------
__global__ void k_final(const float* __restrict__ x, const float* __restrict__ gamma,
                        const float* __restrict__ beta, float* __restrict__ out, int N) {
    long long i = (long long)blockIdx.x * blockDim.x + threadIdx.x;
    long long total = (long long)N * 32;
    if (i >= total) return;
    int c4 = (int)(i & 31);
    float invN = 1.0f / (float)N;
    float4 v  = ((float4*)out)[i];
    float4 xv = ((const float4*)x)[i];
    float r[4] = {v.x, v.y, v.z, v.w};
    float xr[4] = {xv.x, xv.y, xv.z, xv.w};
#pragma unroll
    for (int c = 0; c < 4; c++) {
        int col = c4 * 4 + c;
        float mu  = g_stats[col] * invN;
        float var = g_stats[D + col] * invN - mu * mu;
        float inv = rsqrtf(var + BN_EPS);
        float y = __ldg(&gamma[col]) * (r[c] - mu) * inv + __ldg(&beta[col]);
        y = fmaxf(y, 0.0f);
        r[c] = y + xr[c];
    }
    ((float4*)out)[i] = make_float4(r[0], r[1], r[2], r[3]);
}

// ---------------- launcher --------------------------------------------------------
extern "C" void kernel_launch(void* const* d_in, const int* in_sizes, int n_in,
                              void* d_out, int out_size) {
    const float* x     = (const float*)d_in[0];
    const float* W     = (const float*)d_in[1];
    const float* bias  = (const float*)d_in[2];
    const float* gamma = (const float*)d_in[3];
    const float* beta  = (const float*)d_in[4];
    const void*  ei    = d_in[5];
    int N = in_sizes[0] / D;
    int E = in_sizes[5] / 2;
    float* out = (float*)d_out;

    cudaFuncSetAttribute(k_gemm_mma, cudaFuncAttributeMaxDynamicSharedMemorySize, SM_TOT);

    k_detect<<<1, 1>>>((const int*)ei, E);
    k_init<<<(N + 255) / 256, 256>>>(N);
    k_hist<<<(E + 255) / 256, 256>>>(ei, E);
    int nblk = (N + 1023) / 1024;
    k_scan1<<<nblk, 1024>>>(N);
    k_scan2<<<1, 128>>>(nblk);
    k_scan3<<<(N + 255) / 256, 256>>>(N);
    k_fill<<<(E + 255) / 256, 256>>>(ei, E);
    k_wsplit<<<64, 256>>>(W);
    k_gemm_mma<<<(N + 127) / 128, 256, SM_TOT>>>(x, N);
    k_agg<<<(int)(((long long)N * 32 + 255) / 256), 256>>>(bias, out, N);
    k_stats<<<512, 256>>>(out, N);
    k_final<<<(int)(((long long)N * 32 + 255) / 256), 256>>>(x, gamma, beta, out, N);
}

// round 5
// speedup vs baseline: 1.5887x; 1.1863x over previous
#include <cuda_runtime.h>
#include <cuda_bf16.h>
#include <cstdint>

#define NNODES 100000
#define D 128
#define EMAX 2000000
#define BN_EPS 1e-5f

// ---------------- device scratch (no dynamic allocation allowed) ----------------
__device__ float g_h[(size_t)NNODES * D];     // h' = dinv * (x @ W^T)  (51.2 MB)
__device__ float g_dinv[NNODES];              // 1/sqrt(deg)
__device__ int   g_counts[NNODES];            // in-degree (excluding self loop)
__device__ int   g_rowstart[NNODES];          // CSR row offsets
__device__ int   g_cursor[NNODES];            // fill cursors
__device__ int   g_csr[EMAX];                 // CSR column (src) indices
__device__ int   g_blocksums[128];            // scan partials
__device__ float g_stats[2 * D];              // sums / sumsq
__device__ int   g_is64;                      // edge_index dtype flag
// W split into bf16 hi/lo, stored pre-swizzled (ldmatrix layout), 32KB each
__device__ __align__(16) __nv_bfloat16 g_Whi_img[16384];
__device__ __align__(16) __nv_bfloat16 g_Wlo_img[16384];

// ---------------- warp-mma helpers (plain sm_80+ PTX, no 'a'-gated features) -----
__device__ __forceinline__ uint32_t smem_u32(const void* p) {
    uint32_t a;
    asm("{ .reg .u64 t; cvta.to.shared.u64 t, %1; cvt.u32.u64 %0, t; }" : "=r"(a) : "l"(p));
    return a;
}
__device__ __forceinline__ void ldm_x4(uint32_t& r0, uint32_t& r1, uint32_t& r2, uint32_t& r3,
                                       uint32_t addr) {
    asm volatile("ldmatrix.sync.aligned.m8n8.x4.shared.b16 {%0,%1,%2,%3}, [%4];"
                 : "=r"(r0), "=r"(r1), "=r"(r2), "=r"(r3) : "r"(addr));
}
__device__ __forceinline__ void mma_bf16(float* c, const uint32_t* a, const uint32_t* b) {
    asm volatile(
        "mma.sync.aligned.m16n8k16.row.col.f32.bf16.bf16.f32 "
        "{%0,%1,%2,%3},{%4,%5,%6,%7},{%8,%9},{%0,%1,%2,%3};"
        : "+f"(c[0]), "+f"(c[1]), "+f"(c[2]), "+f"(c[3])
        : "r"(a[0]), "r"(a[1]), "r"(a[2]), "r"(a[3]), "r"(b[0]), "r"(b[1]));
}

// ---------------- edge index access (dtype detected at runtime) ----------------
__device__ __forceinline__ int edge_at(const void* ei, long long pos) {
    if (g_is64) return (int)((const long long*)ei)[pos];
    return ((const int*)ei)[pos];
}

__global__ void k_detect(const int* ei32, int E) {
    int all0 = 1;
    int lim = (E < 64) ? E : 64;
    for (int k = 0; k < lim; k++)
        if (ei32[2 * k + 1] != 0) { all0 = 0; break; }
    g_is64 = all0;
}

__global__ void k_init(int N) {
    int i = blockIdx.x * blockDim.x + threadIdx.x;
    if (i < N) g_counts[i] = 0;
    if (i < 2 * D) g_stats[i] = 0.0f;
}

__global__ void k_hist(const void* ei, int E) {
    int e = blockIdx.x * blockDim.x + threadIdx.x;
    if (e >= E) return;
    int d = edge_at(ei, (long long)E + e);
    atomicAdd(&g_counts[d], 1);
}

// ---- 3-kernel exclusive scan over g_counts -> g_rowstart ----
__global__ void k_scan1(int N) {
    __shared__ int sh[1024];
    int t = threadIdx.x;
    int gid = blockIdx.x * 1024 + t;
    int v = (gid < N) ? g_counts[gid] : 0;
    sh[t] = v;
    __syncthreads();
    for (int off = 1; off < 1024; off <<= 1) {
        int add = (t >= off) ? sh[t - off] : 0;
        __syncthreads();
        sh[t] += add;
        __syncthreads();
    }
    if (gid < N) g_rowstart[gid] = sh[t] - v;
    if (t == 1023) g_blocksums[blockIdx.x] = sh[1023];
}

__global__ void k_scan2(int nblk) {
    __shared__ int sh[128];
    int t = threadIdx.x;
    int v = (t < nblk) ? g_blocksums[t] : 0;
    sh[t] = v;
    __syncthreads();
    for (int off = 1; off < 128; off <<= 1) {
        int add = (t >= off) ? sh[t - off] : 0;
        __syncthreads();
        sh[t] += add;
        __syncthreads();
    }
    if (t < nblk) g_blocksums[t] = sh[t] - v;
}

__global__ void k_scan3(int N) {
    int i = blockIdx.x * blockDim.x + threadIdx.x;
    if (i >= N) return;
    int rs = g_rowstart[i] + g_blocksums[i >> 10];
    g_rowstart[i] = rs;
    g_cursor[i]   = rs;
    g_dinv[i]     = rsqrtf((float)g_counts[i] + 1.0f);
}

__global__ void k_fill(const void* ei, int E) {
    int e = blockIdx.x * blockDim.x + threadIdx.x;
    if (e >= E) return;
    int s = edge_at(ei, e);
    int d = edge_at(ei, (long long)E + e);
    int pos = atomicAdd(&g_cursor[d], 1);
    if (pos < EMAX) g_csr[pos] = s;
}

// ---------------- W split: fp32 -> bf16 hi/lo, ldmatrix-swizzled image -----------
// layout: bf16 index (r*16 + (kc ^ (r&7)))*8 + (k&7),  r=row(n), kc=k>>3
__global__ void k_wsplit(const float* __restrict__ W) {
    int e = blockIdx.x * blockDim.x + threadIdx.x;
    if (e >= 16384) return;
    int r = e >> 7, k = e & 127;
    float w = W[e];
    __nv_bfloat16 hi = __float2bfloat16(w);
    __nv_bfloat16 lo = __float2bfloat16(w - __bfloat162float(hi));
    int kc = k >> 3;
    int idx = (r * 16 + (kc ^ (r & 7))) * 8 + (k & 7);
    g_Whi_img[idx] = hi;
    g_Wlo_img[idx] = lo;
}

// ---------------- GEMM: h' = dinv * (x @ W^T) via mma.sync bf16 3-term split ----
// SMEM: A_hi(32K) A_lo(32K) B_hi(32K) B_lo(32K) = 131072 bytes
#define SM_AHI 0
#define SM_ALO 32768
#define SM_BHI 65536
#define SM_BLO 98304
#define SM_TOT 131072

__global__ __launch_bounds__(256) void k_gemm_mma(const float* __restrict__ x, int N) {
    extern __shared__ char smem[];
    uint32_t sb = smem_u32(smem);
    int tid = threadIdx.x;
    int row0 = blockIdx.x * 128;

    // ---- copy pre-swizzled W hi/lo images (2048 uint4 each) ----
    {
        const uint4* wh = (const uint4*)g_Whi_img;
        const uint4* wl = (const uint4*)g_Wlo_img;
        uint4* bh = (uint4*)(smem + SM_BHI);
        uint4* bl = (uint4*)(smem + SM_BLO);
        for (int i = tid; i < 2048; i += 256) { bh[i] = wh[i]; bl[i] = wl[i]; }
    }

    // ---- convert this tile's x rows to bf16 hi/lo, swizzled ----
    {
        int r  = tid >> 1;          // 0..127
        int hf = tid & 1;           // half-row
        int gr = row0 + r;
        char* Ah = smem + SM_AHI;
        char* Al = smem + SM_ALO;
        if (gr < N) {
            const float4* xr = (const float4*)(x + (size_t)gr * 128) + hf * 16;
#pragma unroll
            for (int j = 0; j < 8; j++) {
                float4 v0 = xr[2 * j];
                float4 v1 = xr[2 * j + 1];
                float f[8] = {v0.x, v0.y, v0.z, v0.w, v1.x, v1.y, v1.z, v1.w};
                uint32_t hw[4], lw[4];
#pragma unroll
                for (int q = 0; q < 4; q++) {
                    float a = f[2 * q], b = f[2 * q + 1];
                    __nv_bfloat16 ha = __float2bfloat16(a);
                    __nv_bfloat16 hb = __float2bfloat16(b);
                    union { __nv_bfloat162 v; uint32_t u; } ch, cl;
                    ch.v = __nv_bfloat162(ha, hb);
                    cl.v = __nv_bfloat162(__float2bfloat16(a - __bfloat162float(ha)),
                                          __float2bfloat16(b - __bfloat162float(hb)));
                    hw[q] = ch.u;
                    lw[q] = cl.u;
                }
                int kc = hf * 8 + j;
                int off = (r * 16 + (kc ^ (r & 7))) * 16;
                *(uint4*)(Ah + off) = make_uint4(hw[0], hw[1], hw[2], hw[3]);
                *(uint4*)(Al + off) = make_uint4(lw[0], lw[1], lw[2], lw[3]);
            }
        } else {
            uint4 z = make_uint4(0, 0, 0, 0);
#pragma unroll
            for (int j = 0; j < 8; j++) {
                int kc = hf * 8 + j;
                int off = (r * 16 + (kc ^ (r & 7))) * 16;
                *(uint4*)(smem + SM_AHI + off) = z;
                *(uint4*)(smem + SM_ALO + off) = z;
            }
        }
    }
    __syncthreads();

    // ---- warp tiles: 8 warps, 4x2 -> warp tile 32(m) x 64(n) ----
    int warp = tid >> 5, lane = tid & 31;
    int wm = warp & 3, wn = warp >> 2;
    int m0 = wm * 32, n0 = wn * 64;
    int sub = lane >> 3, lrow = lane & 7;

    float acc[2][8][4];
#pragma unroll
    for (int mt = 0; mt < 2; mt++)
#pragma unroll
        for (int nt = 0; nt < 8; nt++)
#pragma unroll
            for (int q = 0; q < 4; q++) acc[mt][nt][q] = 0.f;

    int a_row_off = ((sub & 1) << 3) + lrow;
    int a_halfk   = sub >> 1;
    int b_row_off = ((sub & 2) << 2) + lrow;
    int b_halfk   = sub & 1;

#pragma unroll
    for (int ks = 0; ks < 8; ks++) {
        uint32_t ah[2][4], al[2][4], bh[8][2], bl[8][2];
#pragma unroll
        for (int mt = 0; mt < 2; mt++) {
            int r = m0 + mt * 16 + a_row_off;
            int kc = 2 * ks + a_halfk;
            uint32_t addr = (uint32_t)((r * 16 + (kc ^ (r & 7))) * 16);
            ldm_x4(ah[mt][0], ah[mt][1], ah[mt][2], ah[mt][3], sb + SM_AHI + addr);
            ldm_x4(al[mt][0], al[mt][1], al[mt][2], al[mt][3], sb + SM_ALO + addr);
        }
#pragma unroll
        for (int np = 0; np < 4; np++) {
            int r = n0 + np * 16 + b_row_off;
            int kc = 2 * ks + b_halfk;
            uint32_t addr = (uint32_t)((r * 16 + (kc ^ (r & 7))) * 16);
            ldm_x4(bh[2 * np][0], bh[2 * np][1], bh[2 * np + 1][0], bh[2 * np + 1][1],
                   sb + SM_BHI + addr);
            ldm_x4(bl[2 * np][0], bl[2 * np][1], bl[2 * np + 1][0], bl[2 * np + 1][1],
                   sb + SM_BLO + addr);
        }
#pragma unroll
        for (int mt = 0; mt < 2; mt++)
#pragma unroll
            for (int nt = 0; nt < 8; nt++) {
                mma_bf16(acc[mt][nt], ah[mt], bh[nt]);
                mma_bf16(acc[mt][nt], ah[mt], bl[nt]);
                mma_bf16(acc[mt][nt], al[mt], bh[nt]);
            }
    }

    // ---- epilogue: prescale rows by dinv, float2 global stores ----
    int qrow = lane >> 2, qcol = (lane & 3) * 2;
#pragma unroll
    for (int mt = 0; mt < 2; mt++) {
        int r_lo = row0 + m0 + mt * 16 + qrow;
        int r_hi = r_lo + 8;
        float d_lo = (r_lo < N) ? g_dinv[r_lo] : 0.f;
        float d_hi = (r_hi < N) ? g_dinv[r_hi] : 0.f;
#pragma unroll
        for (int nt = 0; nt < 8; nt++) {
            int col = n0 + nt * 8 + qcol;
            if (r_lo < N)
                *(float2*)&g_h[(size_t)r_lo * D + col] =
                    make_float2(d_lo * acc[mt][nt][0], d_lo * acc[mt][nt][1]);
            if (r_hi < N)
                *(float2*)&g_h[(size_t)r_hi * D + col] =
                    make_float2(d_hi * acc[mt][nt][2], d_hi * acc[mt][nt][3]);
        }
    }
}

// ------- aggregation (grid-stride, warp per node) + fused BN statistics ----------
// out[dst] = dinv[dst] * (sum_{src in nbrs} h'[src] + h'[dst]) + b
__global__ __launch_bounds__(256) void k_agg(const float* __restrict__ bias,
                                             float* __restrict__ out, int N, int totalWarps) {
    __shared__ float sh_sum[128];
    __shared__ float sh_sq[128];
    int tid = threadIdx.x;
    int lane = tid & 31;
    if (tid < 128) { sh_sum[tid] = 0.f; sh_sq[tid] = 0.f; }
    __syncthreads();

    int gwarp = blockIdx.x * 8 + (tid >> 5);
    const float4* h4 = (const float4*)g_h;
    float4 bb = ((const float4*)bias)[lane];
    float4 ssum = make_float4(0.f, 0.f, 0.f, 0.f);
    float4 ssq  = make_float4(0.f, 0.f, 0.f, 0.f);

    for (int node = gwarp; node < N; node += totalWarps) {
        int   base = g_rowstart[node];
        int   cnt  = g_counts[node];
        float di   = g_dinv[node];

        float4 acc = h4[(size_t)node * 32 + lane];   // self term h'[dst]

        for (int j0 = 0; j0 < cnt; j0 += 32) {
            int myj = j0 + lane;
            int s = (myj < cnt) ? g_csr[base + myj] : 0;
            int m = min(32, cnt - j0);
            for (int t = 0; t < m; t++) {
                int sv = __shfl_sync(0xffffffffu, s, t);
                float4 hv = h4[(size_t)sv * 32 + lane];
                acc.x += hv.x;
                acc.y += hv.y;
                acc.z += hv.z;
                acc.w += hv.w;
            }
        }
        float4 o;
        o.x = di * acc.x + bb.x;
        o.y = di * acc.y + bb.y;
        o.z = di * acc.z + bb.z;
        o.w = di * acc.w + bb.w;
        ((float4*)out)[(size_t)node * 32 + lane] = o;
        ssum.x += o.x; ssum.y += o.y; ssum.z += o.z; ssum.w += o.w;
        ssq.x += o.x * o.x; ssq.y += o.y * o.y; ssq.z += o.z * o.z; ssq.w += o.w * o.w;
    }

    // block-level reduction into shared, then one global atomic per feature
    atomicAdd(&sh_sum[lane * 4 + 0], ssum.x);
    atomicAdd(&sh_sum[lane * 4 + 1], ssum.y);
    atomicAdd(&sh_sum[lane * 4 + 2], ssum.z);
    atomicAdd(&sh_sum[lane * 4 + 3], ssum.w);
    atomicAdd(&sh_sq[lane * 4 + 0], ssq.x);
    atomicAdd(&sh_sq[lane * 4 + 1], ssq.y);
    atomicAdd(&sh_sq[lane * 4 + 2], ssq.z);
    atomicAdd(&sh_sq[lane * 4 + 3], ssq.w);
    __syncthreads();
    if (tid < 128) {
        atomicAdd(&g_stats[tid], sh_sum[tid]);
        atomicAdd(&g_stats[D + tid], sh_sq[tid]);
    }
}

// ---------------- BN + ReLU + residual -------------------------------------------
__global__ void k_final(const float* __restrict__ x, const float* __restrict__ gamma,
                        const float* __restrict__ beta, float* __restrict__ out, int N) {
    long long i = (long long)blockIdx.x * blockDim.x + threadIdx.x;
    long long total = (long long)N * 32;
    if (i >= total) return;
    int c4 = (int)(i & 31);
    float invN = 1.0f / (float)N;
    float4 v  = ((float4*)out)[i];
    float4 xv = ((const float4*)x)[i];
    float r[4] = {v.x, v.y, v.z, v.w};
    float xr[4] = {xv.x, xv.y, xv.z, xv.w};
#pragma unroll
    for (int c = 0; c < 4; c++) {
        int col = c4 * 4 + c;
        float mu  = g_stats[col] * invN;
        float var = g_stats[D + col] * invN - mu * mu;
        float inv = rsqrtf(var + BN_EPS);
        float y = __ldg(&gamma[col]) * (r[c] - mu) * inv + __ldg(&beta[col]);
        y = fmaxf(y, 0.0f);
        r[c] = y + xr[c];
    }
    ((float4*)out)[i] = make_float4(r[0], r[1], r[2], r[3]);
}

// ---------------- launcher --------------------------------------------------------
extern "C" void kernel_launch(void* const* d_in, const int* in_sizes, int n_in,
                              void* d_out, int out_size) {
    const float* x     = (const float*)d_in[0];
    const float* W     = (const float*)d_in[1];
    const float* bias  = (const float*)d_in[2];
    const float* gamma = (const float*)d_in[3];
    const float* beta  = (const float*)d_in[4];
    const void*  ei    = d_in[5];
    int N = in_sizes[0] / D;
    int E = in_sizes[5] / 2;
    float* out = (float*)d_out;

    cudaFuncSetAttribute(k_gemm_mma, cudaFuncAttributeMaxDynamicSharedMemorySize, SM_TOT);

    k_detect<<<1, 1>>>((const int*)ei, E);
    k_init<<<(N + 255) / 256, 256>>>(N);
    k_hist<<<(E + 255) / 256, 256>>>(ei, E);
    int nblk = (N + 1023) / 1024;
    k_scan1<<<nblk, 1024>>>(N);
    k_scan2<<<1, 128>>>(nblk);
    k_scan3<<<(N + 255) / 256, 256>>>(N);
    k_fill<<<(E + 255) / 256, 256>>>(ei, E);
    k_wsplit<<<64, 256>>>(W);
    k_gemm_mma<<<(N + 127) / 128, 256, SM_TOT>>>(x, N);
    int aggBlocks = 1036;                       // 7 blocks/SM * 148
    k_agg<<<aggBlocks, 256>>>(bias, out, N, aggBlocks * 8);
    k_final<<<(int)(((long long)N * 32 + 255) / 256), 256>>>(x, gamma, beta, out, N);
}

// round 6
// speedup vs baseline: 1.7247x; 1.0856x over previous
#include <cuda_runtime.h>
#include <cuda_bf16.h>
#include <cstdint>

#define NNODES 100000
#define D 128
#define EMAX 2000000
#define BN_EPS 1e-5f

// ---------------- device scratch (no dynamic allocation allowed) ----------------
__device__ float g_h[(size_t)NNODES * D];     // h' = dinv * (x @ W^T)  (51.2 MB)
__device__ float g_dinv[NNODES];              // 1/sqrt(deg)
__device__ int   g_counts[NNODES];            // in-degree (excluding self loop)
__device__ int   g_rowstart[NNODES];          // CSR row offsets
__device__ int   g_cursor[NNODES];            // fill cursors
__device__ int   g_csr[EMAX];                 // CSR column (src) indices
__device__ int   g_blocksums[128];            // scan partials
__device__ float g_stats[2 * D];              // sums / sumsq
__device__ int   g_is64;                      // edge_index dtype flag
// W split into bf16 hi/lo, stored pre-swizzled (ldmatrix layout), 32KB each
__device__ __align__(16) __nv_bfloat16 g_Whi_img[16384];
__device__ __align__(16) __nv_bfloat16 g_Wlo_img[16384];

// ---------------- warp-mma helpers (plain sm_80+ PTX, no 'a'-gated features) -----
__device__ __forceinline__ uint32_t smem_u32(const void* p) {
    uint32_t a;
    asm("{ .reg .u64 t; cvta.to.shared.u64 t, %1; cvt.u32.u64 %0, t; }" : "=r"(a) : "l"(p));
    return a;
}
__device__ __forceinline__ void ldm_x4(uint32_t& r0, uint32_t& r1, uint32_t& r2, uint32_t& r3,
                                       uint32_t addr) {
    asm volatile("ldmatrix.sync.aligned.m8n8.x4.shared.b16 {%0,%1,%2,%3}, [%4];"
                 : "=r"(r0), "=r"(r1), "=r"(r2), "=r"(r3) : "r"(addr));
}
__device__ __forceinline__ void mma_bf16(float* c, const uint32_t* a, const uint32_t* b) {
    asm volatile(
        "mma.sync.aligned.m16n8k16.row.col.f32.bf16.bf16.f32 "
        "{%0,%1,%2,%3},{%4,%5,%6,%7},{%8,%9},{%0,%1,%2,%3};"
        : "+f"(c[0]), "+f"(c[1]), "+f"(c[2]), "+f"(c[3])
        : "r"(a[0]), "r"(a[1]), "r"(a[2]), "r"(a[3]), "r"(b[0]), "r"(b[1]));
}

// ---------------- edge index access (dtype detected at runtime) ----------------
__device__ __forceinline__ int edge_at(const void* ei, long long pos) {
    if (g_is64) return (int)((const long long*)ei)[pos];
    return ((const int*)ei)[pos];
}

// init counters + parallel int64 detection (warp 0 of block 0)
__global__ void k_init(const int* ei32, int E, int N) {
    int i = blockIdx.x * blockDim.x + threadIdx.x;
    if (blockIdx.x == 0 && threadIdx.x < 32) {
        // int64 little-endian => odd int32 words of first 64 pairs are all zero
        int lane = threadIdx.x;
        int bad = 0;
        if (lane < E && ei32[2 * lane + 1] != 0) bad = 1;
        int k2 = lane + 32;
        if (k2 < E && k2 < 64 && ei32[2 * k2 + 1] != 0) bad = 1;
        unsigned m = __ballot_sync(0xffffffffu, bad);
        if (lane == 0) g_is64 = (m == 0u);
    }
    if (i < N) g_counts[i] = 0;
    if (i < 2 * D) g_stats[i] = 0.0f;
}

__global__ void k_hist(const void* ei, int E) {
    int e = blockIdx.x * blockDim.x + threadIdx.x;
    if (e >= E) return;
    int d = edge_at(ei, (long long)E + e);
    atomicAdd(&g_counts[d], 1);
}

// ---- 3-kernel exclusive scan over g_counts -> g_rowstart (shuffle-based) ----
__global__ void k_scan1(int N) {
    __shared__ int warp_off[32];
    int t = threadIdx.x;
    int gid = blockIdx.x * 1024 + t;
    int v = (gid < N) ? g_counts[gid] : 0;
    int lane = t & 31, wid = t >> 5;
    int s = v;
#pragma unroll
    for (int off = 1; off < 32; off <<= 1) {
        int n2 = __shfl_up_sync(0xffffffffu, s, off);
        if (lane >= off) s += n2;
    }
    if (lane == 31) warp_off[wid] = s;
    __syncthreads();
    if (wid == 0) {
        int ws = warp_off[lane];
        int ss = ws;
#pragma unroll
        for (int off = 1; off < 32; off <<= 1) {
            int n2 = __shfl_up_sync(0xffffffffu, ss, off);
            if (lane >= off) ss += n2;
        }
        warp_off[lane] = ss - ws;            // exclusive offset per warp
        if (lane == 31) g_blocksums[blockIdx.x] = ss;   // block total
    }
    __syncthreads();
    if (gid < N) g_rowstart[gid] = s + warp_off[wid] - v;   // exclusive
}

__global__ void k_scan2(int nblk) {
    __shared__ int sh[128];
    int t = threadIdx.x;
    int v = (t < nblk) ? g_blocksums[t] : 0;
    sh[t] = v;
    __syncthreads();
    for (int off = 1; off < 128; off <<= 1) {
        int add = (t >= off) ? sh[t - off] : 0;
        __syncthreads();
        sh[t] += add;
        __syncthreads();
    }
    if (t < nblk) g_blocksums[t] = sh[t] - v;
}

__global__ void k_scan3(int N) {
    int i = blockIdx.x * blockDim.x + threadIdx.x;
    if (i >= N) return;
    int rs = g_rowstart[i] + g_blocksums[i >> 10];
    g_rowstart[i] = rs;
    g_cursor[i]   = rs;
    g_dinv[i]     = rsqrtf((float)g_counts[i] + 1.0f);
}

__global__ void k_fill(const void* ei, int E) {
    int e = blockIdx.x * blockDim.x + threadIdx.x;
    if (e >= E) return;
    int s = edge_at(ei, e);
    int d = edge_at(ei, (long long)E + e);
    int pos = atomicAdd(&g_cursor[d], 1);
    if (pos < EMAX) g_csr[pos] = s;
}

// ---------------- W split: fp32 -> bf16 hi/lo, ldmatrix-swizzled image -----------
// layout: bf16 index (r*16 + (kc ^ (r&7)))*8 + (k&7),  r=row(n), kc=k>>3
__global__ void k_wsplit(const float* __restrict__ W) {
    int e = blockIdx.x * blockDim.x + threadIdx.x;
    if (e >= 16384) return;
    int r = e >> 7, k = e & 127;
    float w = W[e];
    __nv_bfloat16 hi = __float2bfloat16(w);
    __nv_bfloat16 lo = __float2bfloat16(w - __bfloat162float(hi));
    int kc = k >> 3;
    int idx = (r * 16 + (kc ^ (r & 7))) * 8 + (k & 7);
    g_Whi_img[idx] = hi;
    g_Wlo_img[idx] = lo;
}

// ------ GEMM: h' = dinv * (x @ W^T), 64-row tiles for 2 CTAs/SM ------------------
// SMEM: A_hi(16K) A_lo(16K) B_hi(32K) B_lo(32K) = 98304 bytes
#define SM_AHI 0
#define SM_ALO 16384
#define SM_BHI 32768
#define SM_BLO 65536
#define SM_TOT 98304

__global__ __launch_bounds__(256) void k_gemm_mma(const float* __restrict__ x, int N) {
    extern __shared__ char smem[];
    uint32_t sb = smem_u32(smem);
    int tid = threadIdx.x;
    int row0 = blockIdx.x * 64;

    // ---- copy pre-swizzled W hi/lo images (2048 uint4 each) ----
    {
        const uint4* wh = (const uint4*)g_Whi_img;
        const uint4* wl = (const uint4*)g_Wlo_img;
        uint4* bh = (uint4*)(smem + SM_BHI);
        uint4* bl = (uint4*)(smem + SM_BLO);
        for (int i = tid; i < 2048; i += 256) { bh[i] = wh[i]; bl[i] = wl[i]; }
    }

    // ---- convert this tile's 64 x rows to bf16 hi/lo, swizzled ----
    // 4 threads/row, each handles 4 kc-chunks (8 floats each)
    {
        int r = tid >> 2;           // 0..63
        int q = tid & 3;            // quarter-row
        int gr = row0 + r;
        char* Ah = smem + SM_AHI;
        char* Al = smem + SM_ALO;
        if (gr < N) {
            const float4* xr = (const float4*)(x + (size_t)gr * 128) + q * 8;
#pragma unroll
            for (int j = 0; j < 4; j++) {
                float4 v0 = xr[2 * j];
                float4 v1 = xr[2 * j + 1];
                float f[8] = {v0.x, v0.y, v0.z, v0.w, v1.x, v1.y, v1.z, v1.w};
                uint32_t hw[4], lw[4];
#pragma unroll
                for (int p = 0; p < 4; p++) {
                    float a = f[2 * p], b = f[2 * p + 1];
                    __nv_bfloat16 ha = __float2bfloat16(a);
                    __nv_bfloat16 hb = __float2bfloat16(b);
                    union { __nv_bfloat162 v; uint32_t u; } ch, cl;
                    ch.v = __nv_bfloat162(ha, hb);
                    cl.v = __nv_bfloat162(__float2bfloat16(a - __bfloat162float(ha)),
                                          __float2bfloat16(b - __bfloat162float(hb)));
                    hw[p] = ch.u;
                    lw[p] = cl.u;
                }
                int kc = q * 4 + j;
                int off = (r * 16 + (kc ^ (r & 7))) * 16;
                *(uint4*)(Ah + off) = make_uint4(hw[0], hw[1], hw[2], hw[3]);
                *(uint4*)(Al + off) = make_uint4(lw[0], lw[1], lw[2], lw[3]);
            }
        } else {
            uint4 z = make_uint4(0, 0, 0, 0);
#pragma unroll
            for (int j = 0; j < 4; j++) {
                int kc = q * 4 + j;
                int off = (r * 16 + (kc ^ (r & 7))) * 16;
                *(uint4*)(smem + SM_AHI + off) = z;
                *(uint4*)(smem + SM_ALO + off) = z;
            }
        }
    }
    __syncthreads();

    // ---- 8 warps: 2(m) x 4(n) -> warp tile 32(m) x 32(n) ----
    int warp = tid >> 5, lane = tid & 31;
    int wm = warp & 1, wn = warp >> 1;
    int m0 = wm * 32, n0 = wn * 32;
    int sub = lane >> 3, lrow = lane & 7;

    float acc[2][4][4];
#pragma unroll
    for (int mt = 0; mt < 2; mt++)
#pragma unroll
        for (int nt = 0; nt < 4; nt++)
#pragma unroll
            for (int q = 0; q < 4; q++) acc[mt][nt][q] = 0.f;

    int a_row_off = ((sub & 1) << 3) + lrow;
    int a_halfk   = sub >> 1;
    int b_row_off = ((sub & 2) << 2) + lrow;
    int b_halfk   = sub & 1;

#pragma unroll
    for (int ks = 0; ks < 8; ks++) {
        uint32_t ah[2][4], al[2][4], bh[4][2], bl[4][2];
#pragma unroll
        for (int mt = 0; mt < 2; mt++) {
            int r = m0 + mt * 16 + a_row_off;
            int kc = 2 * ks + a_halfk;
            uint32_t addr = (uint32_t)((r * 16 + (kc ^ (r & 7))) * 16);
            ldm_x4(ah[mt][0], ah[mt][1], ah[mt][2], ah[mt][3], sb + SM_AHI + addr);
            ldm_x4(al[mt][0], al[mt][1], al[mt][2], al[mt][3], sb + SM_ALO + addr);
        }
#pragma unroll
        for (int np = 0; np < 2; np++) {
            int r = n0 + np * 16 + b_row_off;
            int kc = 2 * ks + b_halfk;
            uint32_t addr = (uint32_t)((r * 16 + (kc ^ (r & 7))) * 16);
            ldm_x4(bh[2 * np][0], bh[2 * np][1], bh[2 * np + 1][0], bh[2 * np + 1][1],
                   sb + SM_BHI + addr);
            ldm_x4(bl[2 * np][0], bl[2 * np][1], bl[2 * np + 1][0], bl[2 * np + 1][1],
                   sb + SM_BLO + addr);
        }
#pragma unroll
        for (int mt = 0; mt < 2; mt++)
#pragma unroll
            for (int nt = 0; nt < 4; nt++) {
                mma_bf16(acc[mt][nt], ah[mt], bh[nt]);
                mma_bf16(acc[mt][nt], ah[mt], bl[nt]);
                mma_bf16(acc[mt][nt], al[mt], bh[nt]);
            }
    }

    // ---- epilogue: prescale rows by dinv, float2 global stores ----
    int qrow = lane >> 2, qcol = (lane & 3) * 2;
#pragma unroll
    for (int mt = 0; mt < 2; mt++) {
        int r_lo = row0 + m0 + mt * 16 + qrow;
        int r_hi = r_lo + 8;
        float d_lo = (r_lo < N) ? g_dinv[r_lo] : 0.f;
        float d_hi = (r_hi < N) ? g_dinv[r_hi] : 0.f;
#pragma unroll
        for (int nt = 0; nt < 4; nt++) {
            int col = n0 + nt * 8 + qcol;
            if (r_lo < N)
                *(float2*)&g_h[(size_t)r_lo * D + col] =
                    make_float2(d_lo * acc[mt][nt][0], d_lo * acc[mt][nt][1]);
            if (r_hi < N)
                *(float2*)&g_h[(size_t)r_hi * D + col] =
                    make_float2(d_hi * acc[mt][nt][2], d_hi * acc[mt][nt][3]);
        }
    }
}

// ------- aggregation (grid-stride, warp per node) + fused BN statistics ----------
// out[dst] = dinv[dst] * (sum_{src in nbrs} h'[src] + h'[dst]) + b
__global__ __launch_bounds__(256) void k_agg(const float* __restrict__ bias,
                                             float* __restrict__ out, int N, int totalWarps) {
    __shared__ float sh_sum[128];
    __shared__ float sh_sq[128];
    int tid = threadIdx.x;
    int lane = tid & 31;
    if (tid < 128) { sh_sum[tid] = 0.f; sh_sq[tid] = 0.f; }
    __syncthreads();

    int gwarp = blockIdx.x * 8 + (tid >> 5);
    const float4* h4 = (const float4*)g_h;
    float4 bb = ((const float4*)bias)[lane];
    float4 ssum = make_float4(0.f, 0.f, 0.f, 0.f);
    float4 ssq  = make_float4(0.f, 0.f, 0.f, 0.f);

    for (int node = gwarp; node < N; node += totalWarps) {
        int   base = g_rowstart[node];
        int   cnt  = g_counts[node];
        float di   = g_dinv[node];

        float4 acc  = h4[(size_t)node * 32 + lane];   // self term h'[dst]
        float4 acc2 = make_float4(0.f, 0.f, 0.f, 0.f);

        for (int j0 = 0; j0 < cnt; j0 += 32) {
            int myj = j0 + lane;
            int s = (myj < cnt) ? g_csr[base + myj] : 0;
            int m = min(32, cnt - j0);
            int t = 0;
            // 2-way unrolled: two independent gathers in flight
            for (; t + 2 <= m; t += 2) {
                int sv0 = __shfl_sync(0xffffffffu, s, t);
                int sv1 = __shfl_sync(0xffffffffu, s, t + 1);
                float4 h0 = h4[(size_t)sv0 * 32 + lane];
                float4 h1 = h4[(size_t)sv1 * 32 + lane];
                acc.x += h0.x;  acc.y += h0.y;  acc.z += h0.z;  acc.w += h0.w;
                acc2.x += h1.x; acc2.y += h1.y; acc2.z += h1.z; acc2.w += h1.w;
            }
            if (t < m) {
                int sv0 = __shfl_sync(0xffffffffu, s, t);
                float4 h0 = h4[(size_t)sv0 * 32 + lane];
                acc.x += h0.x; acc.y += h0.y; acc.z += h0.z; acc.w += h0.w;
            }
        }
        float4 o;
        o.x = di * (acc.x + acc2.x) + bb.x;
        o.y = di * (acc.y + acc2.y) + bb.y;
        o.z = di * (acc.z + acc2.z) + bb.z;
        o.w = di * (acc.w + acc2.w) + bb.w;
        ((float4*)out)[(size_t)node * 32 + lane] = o;
        ssum.x += o.x; ssum.y += o.y; ssum.z += o.z; ssum.w += o.w;
        ssq.x += o.x * o.x; ssq.y += o.y * o.y; ssq.z += o.z * o.z; ssq.w += o.w * o.w;
    }

    atomicAdd(&sh_sum[lane * 4 + 0], ssum.x);
    atomicAdd(&sh_sum[lane * 4 + 1], ssum.y);
    atomicAdd(&sh_sum[lane * 4 + 2], ssum.z);
    atomicAdd(&sh_sum[lane * 4 + 3], ssum.w);
    atomicAdd(&sh_sq[lane * 4 + 0], ssq.x);
    atomicAdd(&sh_sq[lane * 4 + 1], ssq.y);
    atomicAdd(&sh_sq[lane * 4 + 2], ssq.z);
    atomicAdd(&sh_sq[lane * 4 + 3], ssq.w);
    __syncthreads();
    if (tid < 128) {
        atomicAdd(&g_stats[tid], sh_sum[tid]);
        atomicAdd(&g_stats[D + tid], sh_sq[tid]);
    }
}

// ---------------- BN + ReLU + residual -------------------------------------------
__global__ void k_final(const float* __restrict__ x, const float* __restrict__ gamma,
                        const float* __restrict__ beta, float* __restrict__ out, int N) {
    long long i = (long long)blockIdx.x * blockDim.x + threadIdx.x;
    long long total = (long long)N * 32;
    if (i >= total) return;
    int c4 = (int)(i & 31);
    float invN = 1.0f / (float)N;
    float4 v  = ((float4*)out)[i];
    float4 xv = ((const float4*)x)[i];
    float r[4] = {v.x, v.y, v.z, v.w};
    float xr[4] = {xv.x, xv.y, xv.z, xv.w};
#pragma unroll
    for (int c = 0; c < 4; c++) {
        int col = c4 * 4 + c;
        float mu  = g_stats[col] * invN;
        float var = g_stats[D + col] * invN - mu * mu;
        float inv = rsqrtf(var + BN_EPS);
        float y = __ldg(&gamma[col]) * (r[c] - mu) * inv + __ldg(&beta[col]);
        y = fmaxf(y, 0.0f);
        r[c] = y + xr[c];
    }
    ((float4*)out)[i] = make_float4(r[0], r[1], r[2], r[3]);
}

// ---------------- launcher --------------------------------------------------------
extern "C" void kernel_launch(void* const* d_in, const int* in_sizes, int n_in,
                              void* d_out, int out_size) {
    const float* x     = (const float*)d_in[0];
    const float* W     = (const float*)d_in[1];
    const float* bias  = (const float*)d_in[2];
    const float* gamma = (const float*)d_in[3];
    const float* beta  = (const float*)d_in[4];
    const void*  ei    = d_in[5];
    int N = in_sizes[0] / D;
    int E = in_sizes[5] / 2;
    float* out = (float*)d_out;

    cudaFuncSetAttribute(k_gemm_mma, cudaFuncAttributeMaxDynamicSharedMemorySize, SM_TOT);

    k_init<<<(N + 255) / 256, 256>>>((const int*)ei, E, N);
    k_hist<<<(E + 255) / 256, 256>>>(ei, E);
    int nblk = (N + 1023) / 1024;
    k_scan1<<<nblk, 1024>>>(N);
    k_scan2<<<1, 128>>>(nblk);
    k_scan3<<<(N + 255) / 256, 256>>>(N);
    k_fill<<<(E + 255) / 256, 256>>>(ei, E);
    k_wsplit<<<64, 256>>>(W);
    k_gemm_mma<<<(N + 63) / 64, 256, SM_TOT>>>(x, N);
    int aggBlocks = 1036;                       // 7 blocks/SM * 148
    k_agg<<<aggBlocks, 256>>>(bias, out, N, aggBlocks * 8);
    k_final<<<(int)(((long long)N * 32 + 255) / 256), 256>>>(x, gamma, beta, out, N);
}

// round 7
// speedup vs baseline: 1.8356x; 1.0643x over previous
#include <cuda_runtime.h>
#include <cuda_bf16.h>
#include <cstdint>

#define NNODES 100000
#define D 128
#define EMAX 2000000
#define BN_EPS 1e-5f

// ---------------- device scratch (no dynamic allocation allowed) ----------------
__device__ float g_h[(size_t)NNODES * D];     // h' = dinv * (x @ W^T)  (51.2 MB)
__device__ float g_dinv[NNODES];              // 1/sqrt(deg)
__device__ int   g_counts[NNODES];            // in-degree (excluding self loop)
__device__ int   g_rowstart[NNODES];          // CSR row offsets
__device__ int   g_cursor[NNODES];            // fill cursors
__device__ int   g_csr[EMAX];                 // CSR column (src) indices
__device__ int   g_blocksums[128];            // scan partials (per scan1 block)
__device__ float g_stats[2 * D];              // sums / sumsq
__device__ int   g_is64;                      // edge_index dtype flag
// W split into bf16 hi/lo, stored pre-swizzled (ldmatrix layout), 32KB each
__device__ __align__(16) __nv_bfloat16 g_Whi_img[16384];
__device__ __align__(16) __nv_bfloat16 g_Wlo_img[16384];

// ---------------- warp-mma helpers (plain sm_80+ PTX, no 'a'-gated features) -----
__device__ __forceinline__ uint32_t smem_u32(const void* p) {
    uint32_t a;
    asm("{ .reg .u64 t; cvta.to.shared.u64 t, %1; cvt.u32.u64 %0, t; }" : "=r"(a) : "l"(p));
    return a;
}
__device__ __forceinline__ void ldm_x4(uint32_t& r0, uint32_t& r1, uint32_t& r2, uint32_t& r3,
                                       uint32_t addr) {
    asm volatile("ldmatrix.sync.aligned.m8n8.x4.shared.b16 {%0,%1,%2,%3}, [%4];"
                 : "=r"(r0), "=r"(r1), "=r"(r2), "=r"(r3) : "r"(addr));
}
__device__ __forceinline__ void mma_bf16(float* c, const uint32_t* a, const uint32_t* b) {
    asm volatile(
        "mma.sync.aligned.m16n8k16.row.col.f32.bf16.bf16.f32 "
        "{%0,%1,%2,%3},{%4,%5,%6,%7},{%8,%9},{%0,%1,%2,%3};"
        : "+f"(c[0]), "+f"(c[1]), "+f"(c[2]), "+f"(c[3])
        : "r"(a[0]), "r"(a[1]), "r"(a[2]), "r"(a[3]), "r"(b[0]), "r"(b[1]));
}

// ---------------- edge index access (dtype detected at runtime) ----------------
__device__ __forceinline__ int edge_at(const void* ei, long long pos) {
    if (g_is64) return (int)((const long long*)ei)[pos];
    return ((const int*)ei)[pos];
}

// init counters + parallel int64 detection + fused W hi/lo split
__global__ void k_init(const int* ei32, const float* __restrict__ W, int E, int N) {
    int i = blockIdx.x * blockDim.x + threadIdx.x;
    if (blockIdx.x == 0 && threadIdx.x < 32) {
        // int64 little-endian => odd int32 words of first 64 pairs are all zero
        int lane = threadIdx.x;
        int bad = 0;
        if (lane < E && ei32[2 * lane + 1] != 0) bad = 1;
        int k2 = lane + 32;
        if (k2 < E && k2 < 64 && ei32[2 * k2 + 1] != 0) bad = 1;
        unsigned m = __ballot_sync(0xffffffffu, bad);
        if (lane == 0) g_is64 = (m == 0u);
    }
    if (i < N) g_counts[i] = 0;
    if (i < 2 * D) g_stats[i] = 0.0f;
    // fused W split: fp32 -> bf16 hi/lo, ldmatrix-swizzled image
    if (i < 16384) {
        int r = i >> 7, k = i & 127;
        float w = W[i];
        __nv_bfloat16 hi = __float2bfloat16(w);
        __nv_bfloat16 lo = __float2bfloat16(w - __bfloat162float(hi));
        int kc = k >> 3;
        int idx = (r * 16 + (kc ^ (r & 7))) * 8 + (k & 7);
        g_Whi_img[idx] = hi;
        g_Wlo_img[idx] = lo;
    }
}

__global__ void k_hist(const void* ei, int E) {
    int e = blockIdx.x * blockDim.x + threadIdx.x;
    if (e >= E) return;
    int d = edge_at(ei, (long long)E + e);
    atomicAdd(&g_counts[d], 1);
}

// ---- scan over g_counts -> g_rowstart (2 kernels; scan2 folded into scan3) ----
__global__ void k_scan1(int N) {
    __shared__ int warp_off[32];
    int t = threadIdx.x;
    int gid = blockIdx.x * 1024 + t;
    int v = (gid < N) ? g_counts[gid] : 0;
    int lane = t & 31, wid = t >> 5;
    int s = v;
#pragma unroll
    for (int off = 1; off < 32; off <<= 1) {
        int n2 = __shfl_up_sync(0xffffffffu, s, off);
        if (lane >= off) s += n2;
    }
    if (lane == 31) warp_off[wid] = s;
    __syncthreads();
    if (wid == 0) {
        int ws = warp_off[lane];
        int ss = ws;
#pragma unroll
        for (int off = 1; off < 32; off <<= 1) {
            int n2 = __shfl_up_sync(0xffffffffu, ss, off);
            if (lane >= off) ss += n2;
        }
        warp_off[lane] = ss - ws;            // exclusive offset per warp
        if (lane == 31) g_blocksums[blockIdx.x] = ss;   // block total
    }
    __syncthreads();
    if (gid < N) g_rowstart[gid] = s + warp_off[wid] - v;   // within-block exclusive
}

// scan3: each 256-thread block spans indices sharing one scan1-block b = blockIdx>>2;
// warp 0 reduces the first b block sums (<=128 entries), then all threads add.
__global__ __launch_bounds__(256) void k_scan3(int N) {
    __shared__ int s_off;
    int t = threadIdx.x;
    int b = blockIdx.x >> 2;     // scan1 block index for this whole block
    if (t < 32) {
        int acc = 0;
#pragma unroll
        for (int j = 0; j < 4; j++) {
            int idx = t + j * 32;
            if (idx < b) acc += g_blocksums[idx];
        }
#pragma unroll
        for (int off = 16; off > 0; off >>= 1)
            acc += __shfl_down_sync(0xffffffffu, acc, off);
        if (t == 0) s_off = acc;
    }
    __syncthreads();
    int i = blockIdx.x * 256 + t;
    if (i >= N) return;
    int rs = g_rowstart[i] + s_off;
    g_rowstart[i] = rs;
    g_cursor[i]   = rs;
    g_dinv[i]     = rsqrtf((float)g_counts[i] + 1.0f);
}

__global__ void k_fill(const void* ei, int E) {
    int e = blockIdx.x * blockDim.x + threadIdx.x;
    if (e >= E) return;
    int s = edge_at(ei, e);
    int d = edge_at(ei, (long long)E + e);
    int pos = atomicAdd(&g_cursor[d], 1);
    if (pos < EMAX) g_csr[pos] = s;
}

// ------ GEMM: h' = dinv * (x @ W^T), 64-row tiles for 2 CTAs/SM ------------------
// SMEM: A_hi(16K) A_lo(16K) B_hi(32K) B_lo(32K) = 98304 bytes
#define SM_AHI 0
#define SM_ALO 16384
#define SM_BHI 32768
#define SM_BLO 65536
#define SM_TOT 98304

__global__ __launch_bounds__(256) void k_gemm_mma(const float* __restrict__ x, int N) {
    extern __shared__ char smem[];
    uint32_t sb = smem_u32(smem);
    int tid = threadIdx.x;
    int row0 = blockIdx.x * 64;

    // ---- copy pre-swizzled W hi/lo images (2048 uint4 each) ----
    {
        const uint4* wh = (const uint4*)g_Whi_img;
        const uint4* wl = (const uint4*)g_Wlo_img;
        uint4* bh = (uint4*)(smem + SM_BHI);
        uint4* bl = (uint4*)(smem + SM_BLO);
        for (int i = tid; i < 2048; i += 256) { bh[i] = wh[i]; bl[i] = wl[i]; }
    }

    // ---- convert this tile's 64 x rows to bf16 hi/lo, swizzled ----
    {
        int r = tid >> 2;           // 0..63
        int q = tid & 3;            // quarter-row
        int gr = row0 + r;
        char* Ah = smem + SM_AHI;
        char* Al = smem + SM_ALO;
        if (gr < N) {
            const float4* xr = (const float4*)(x + (size_t)gr * 128) + q * 8;
#pragma unroll
            for (int j = 0; j < 4; j++) {
                float4 v0 = xr[2 * j];
                float4 v1 = xr[2 * j + 1];
                float f[8] = {v0.x, v0.y, v0.z, v0.w, v1.x, v1.y, v1.z, v1.w};
                uint32_t hw[4], lw[4];
#pragma unroll
                for (int p = 0; p < 4; p++) {
                    float a = f[2 * p], b = f[2 * p + 1];
                    __nv_bfloat16 ha = __float2bfloat16(a);
                    __nv_bfloat16 hb = __float2bfloat16(b);
                    union { __nv_bfloat162 v; uint32_t u; } ch, cl;
                    ch.v = __nv_bfloat162(ha, hb);
                    cl.v = __nv_bfloat162(__float2bfloat16(a - __bfloat162float(ha)),
                                          __float2bfloat16(b - __bfloat162float(hb)));
                    hw[p] = ch.u;
                    lw[p] = cl.u;
                }
                int kc = q * 4 + j;
                int off = (r * 16 + (kc ^ (r & 7))) * 16;
                *(uint4*)(Ah + off) = make_uint4(hw[0], hw[1], hw[2], hw[3]);
                *(uint4*)(Al + off) = make_uint4(lw[0], lw[1], lw[2], lw[3]);
            }
        } else {
            uint4 z = make_uint4(0, 0, 0, 0);
#pragma unroll
            for (int j = 0; j < 4; j++) {
                int kc = q * 4 + j;
                int off = (r * 16 + (kc ^ (r & 7))) * 16;
                *(uint4*)(smem + SM_AHI + off) = z;
                *(uint4*)(smem + SM_ALO + off) = z;
            }
        }
    }
    __syncthreads();

    // ---- 8 warps: 2(m) x 4(n) -> warp tile 32(m) x 32(n) ----
    int warp = tid >> 5, lane = tid & 31;
    int wm = warp & 1, wn = warp >> 1;
    int m0 = wm * 32, n0 = wn * 32;
    int sub = lane >> 3, lrow = lane & 7;

    float acc[2][4][4];
#pragma unroll
    for (int mt = 0; mt < 2; mt++)
#pragma unroll
        for (int nt = 0; nt < 4; nt++)
#pragma unroll
            for (int q = 0; q < 4; q++) acc[mt][nt][q] = 0.f;

    int a_row_off = ((sub & 1) << 3) + lrow;
    int a_halfk   = sub >> 1;
    int b_row_off = ((sub & 2) << 2) + lrow;
    int b_halfk   = sub & 1;

#pragma unroll
    for (int ks = 0; ks < 8; ks++) {
        uint32_t ah[2][4], al[2][4], bh[4][2], bl[4][2];
#pragma unroll
        for (int mt = 0; mt < 2; mt++) {
            int r = m0 + mt * 16 + a_row_off;
            int kc = 2 * ks + a_halfk;
            uint32_t addr = (uint32_t)((r * 16 + (kc ^ (r & 7))) * 16);
            ldm_x4(ah[mt][0], ah[mt][1], ah[mt][2], ah[mt][3], sb + SM_AHI + addr);
            ldm_x4(al[mt][0], al[mt][1], al[mt][2], al[mt][3], sb + SM_ALO + addr);
        }
#pragma unroll
        for (int np = 0; np < 2; np++) {
            int r = n0 + np * 16 + b_row_off;
            int kc = 2 * ks + b_halfk;
            uint32_t addr = (uint32_t)((r * 16 + (kc ^ (r & 7))) * 16);
            ldm_x4(bh[2 * np][0], bh[2 * np][1], bh[2 * np + 1][0], bh[2 * np + 1][1],
                   sb + SM_BHI + addr);
            ldm_x4(bl[2 * np][0], bl[2 * np][1], bl[2 * np + 1][0], bl[2 * np + 1][1],
                   sb + SM_BLO + addr);
        }
#pragma unroll
        for (int mt = 0; mt < 2; mt++)
#pragma unroll
            for (int nt = 0; nt < 4; nt++) {
                mma_bf16(acc[mt][nt], ah[mt], bh[nt]);
                mma_bf16(acc[mt][nt], ah[mt], bl[nt]);
                mma_bf16(acc[mt][nt], al[mt], bh[nt]);
            }
    }

    // ---- epilogue: prescale rows by dinv, float2 global stores ----
    int qrow = lane >> 2, qcol = (lane & 3) * 2;
#pragma unroll
    for (int mt = 0; mt < 2; mt++) {
        int r_lo = row0 + m0 + mt * 16 + qrow;
        int r_hi = r_lo + 8;
        float d_lo = (r_lo < N) ? g_dinv[r_lo] : 0.f;
        float d_hi = (r_hi < N) ? g_dinv[r_hi] : 0.f;
#pragma unroll
        for (int nt = 0; nt < 4; nt++) {
            int col = n0 + nt * 8 + qcol;
            if (r_lo < N)
                *(float2*)&g_h[(size_t)r_lo * D + col] =
                    make_float2(d_lo * acc[mt][nt][0], d_lo * acc[mt][nt][1]);
            if (r_hi < N)
                *(float2*)&g_h[(size_t)r_hi * D + col] =
                    make_float2(d_hi * acc[mt][nt][2], d_hi * acc[mt][nt][3]);
        }
    }
}

// ------- aggregation (grid-stride, warp per node) + fused BN statistics ----------
// out[dst] = dinv[dst] * (sum_{src in nbrs} h'[src] + h'[dst]) + b
__global__ __launch_bounds__(256) void k_agg(const float* __restrict__ bias,
                                             float* __restrict__ out, int N, int totalWarps) {
    __shared__ float sh_sum[128];
    __shared__ float sh_sq[128];
    int tid = threadIdx.x;
    int lane = tid & 31;
    if (tid < 128) { sh_sum[tid] = 0.f; sh_sq[tid] = 0.f; }
    __syncthreads();

    int gwarp = blockIdx.x * 8 + (tid >> 5);
    const float4* h4 = (const float4*)g_h;
    float4 bb = ((const float4*)bias)[lane];
    float4 ssum = make_float4(0.f, 0.f, 0.f, 0.f);
    float4 ssq  = make_float4(0.f, 0.f, 0.f, 0.f);

    for (int node = gwarp; node < N; node += totalWarps) {
        int   base = g_rowstart[node];
        int   cnt  = g_counts[node];
        float di   = g_dinv[node];

        float4 a0 = h4[(size_t)node * 32 + lane];   // self term h'[dst]
        float4 a1 = make_float4(0.f, 0.f, 0.f, 0.f);
        float4 a2 = make_float4(0.f, 0.f, 0.f, 0.f);
        float4 a3 = make_float4(0.f, 0.f, 0.f, 0.f);

        for (int j0 = 0; j0 < cnt; j0 += 32) {
            int myj = j0 + lane;
            int s = (myj < cnt) ? g_csr[base + myj] : 0;
            int m = min(32, cnt - j0);
            int t = 0;
            // 4-way unrolled: four independent gathers in flight
            for (; t + 4 <= m; t += 4) {
                int sv0 = __shfl_sync(0xffffffffu, s, t);
                int sv1 = __shfl_sync(0xffffffffu, s, t + 1);
                int sv2 = __shfl_sync(0xffffffffu, s, t + 2);
                int sv3 = __shfl_sync(0xffffffffu, s, t + 3);
                float4 h0 = h4[(size_t)sv0 * 32 + lane];
                float4 h1 = h4[(size_t)sv1 * 32 + lane];
                float4 h2 = h4[(size_t)sv2 * 32 + lane];
                float4 h3 = h4[(size_t)sv3 * 32 + lane];
                a0.x += h0.x; a0.y += h0.y; a0.z += h0.z; a0.w += h0.w;
                a1.x += h1.x; a1.y += h1.y; a1.z += h1.z; a1.w += h1.w;
                a2.x += h2.x; a2.y += h2.y; a2.z += h2.z; a2.w += h2.w;
                a3.x += h3.x; a3.y += h3.y; a3.z += h3.z; a3.w += h3.w;
            }
            for (; t < m; t++) {
                int sv0 = __shfl_sync(0xffffffffu, s, t);
                float4 h0 = h4[(size_t)sv0 * 32 + lane];
                a0.x += h0.x; a0.y += h0.y; a0.z += h0.z; a0.w += h0.w;
            }
        }
        float4 o;
        o.x = di * ((a0.x + a1.x) + (a2.x + a3.x)) + bb.x;
        o.y = di * ((a0.y + a1.y) + (a2.y + a3.y)) + bb.y;
        o.z = di * ((a0.z + a1.z) + (a2.z + a3.z)) + bb.z;
        o.w = di * ((a0.w + a1.w) + (a2.w + a3.w)) + bb.w;
        ((float4*)out)[(size_t)node * 32 + lane] = o;
        ssum.x += o.x; ssum.y += o.y; ssum.z += o.z; ssum.w += o.w;
        ssq.x += o.x * o.x; ssq.y += o.y * o.y; ssq.z += o.z * o.z; ssq.w += o.w * o.w;
    }

    atomicAdd(&sh_sum[lane * 4 + 0], ssum.x);
    atomicAdd(&sh_sum[lane * 4 + 1], ssum.y);
    atomicAdd(&sh_sum[lane * 4 + 2], ssum.z);
    atomicAdd(&sh_sum[lane * 4 + 3], ssum.w);
    atomicAdd(&sh_sq[lane * 4 + 0], ssq.x);
    atomicAdd(&sh_sq[lane * 4 + 1], ssq.y);
    atomicAdd(&sh_sq[lane * 4 + 2], ssq.z);
    atomicAdd(&sh_sq[lane * 4 + 3], ssq.w);
    __syncthreads();
    if (tid < 128) {
        atomicAdd(&g_stats[tid], sh_sum[tid]);
        atomicAdd(&g_stats[D + tid], sh_sq[tid]);
    }
}

// ---------------- BN + ReLU + residual -------------------------------------------
__global__ void k_final(const float* __restrict__ x, const float* __restrict__ gamma,
                        const float* __restrict__ beta, float* __restrict__ out, int N) {
    long long i = (long long)blockIdx.x * blockDim.x + threadIdx.x;
    long long total = (long long)N * 32;
    if (i >= total) return;
    int c4 = (int)(i & 31);
    float invN = 1.0f / (float)N;
    float4 v  = ((float4*)out)[i];
    float4 xv = ((const float4*)x)[i];
    float r[4] = {v.x, v.y, v.z, v.w};
    float xr[4] = {xv.x, xv.y, xv.z, xv.w};
#pragma unroll
    for (int c = 0; c < 4; c++) {
        int col = c4 * 4 + c;
        float mu  = g_stats[col] * invN;
        float var = g_stats[D + col] * invN - mu * mu;
        float inv = rsqrtf(var + BN_EPS);
        float y = __ldg(&gamma[col]) * (r[c] - mu) * inv + __ldg(&beta[col]);
        y = fmaxf(y, 0.0f);
        r[c] = y + xr[c];
    }
    ((float4*)out)[i] = make_float4(r[0], r[1], r[2], r[3]);
}

// ---------------- launcher --------------------------------------------------------
extern "C" void kernel_launch(void* const* d_in, const int* in_sizes, int n_in,
                              void* d_out, int out_size) {
    const float* x     = (const float*)d_in[0];
    const float* W     = (const float*)d_in[1];
    const float* bias  = (const float*)d_in[2];
    const float* gamma = (const float*)d_in[3];
    const float* beta  = (const float*)d_in[4];
    const void*  ei    = d_in[5];
    int N = in_sizes[0] / D;
    int E = in_sizes[5] / 2;
    float* out = (float*)d_out;

    cudaFuncSetAttribute(k_gemm_mma, cudaFuncAttributeMaxDynamicSharedMemorySize, SM_TOT);

    k_init<<<(N + 255) / 256, 256>>>((const int*)ei, W, E, N);
    k_hist<<<(E + 255) / 256, 256>>>(ei, E);
    int nblk = (N + 1023) / 1024;
    k_scan1<<<nblk, 1024>>>(N);
    k_scan3<<<(N + 255) / 256, 256>>>(N);
    k_fill<<<(E + 255) / 256, 256>>>(ei, E);
    k_gemm_mma<<<(N + 63) / 64, 256, SM_TOT>>>(x, N);
    int aggBlocks = 1036;                       // 7 blocks/SM * 148
    k_agg<<<aggBlocks, 256>>>(bias, out, N, aggBlocks * 8);
    k_final<<<(int)(((long long)N * 32 + 255) / 256), 256>>>(x, gamma, beta, out, N);
}

// round 8
// speedup vs baseline: 1.8992x; 1.0346x over previous
#include <cuda_runtime.h>
#include <cuda_bf16.h>
#include <cuda_fp16.h>
#include <cstdint>

#define NNODES 100000
#define D 128
#define EMAX 2000000
#define BN_EPS 1e-5f

// ---------------- device scratch (no dynamic allocation allowed) ----------------
__device__ __half g_hh[(size_t)NNODES * D];   // h' = dinv * (x @ W^T), fp16 (25.6 MB)
__device__ float g_dinv[NNODES];              // 1/sqrt(deg)
__device__ int   g_counts[NNODES];            // in-degree (excluding self loop)
__device__ int   g_rowstart[NNODES];          // CSR row offsets
__device__ int   g_cursor[NNODES];            // fill cursors
__device__ int   g_csr[EMAX];                 // CSR column (src) indices
__device__ int   g_blocksums[128];            // scan partials (per scan1 block)
__device__ float g_stats[2 * D];              // sums / sumsq
__device__ int   g_is64;                      // edge_index dtype flag
// W split into bf16 hi/lo, stored pre-swizzled (ldmatrix layout), 32KB each
__device__ __align__(16) __nv_bfloat16 g_Whi_img[16384];
__device__ __align__(16) __nv_bfloat16 g_Wlo_img[16384];

// ---------------- warp-mma helpers (plain sm_80+ PTX, no 'a'-gated features) -----
__device__ __forceinline__ uint32_t smem_u32(const void* p) {
    uint32_t a;
    asm("{ .reg .u64 t; cvta.to.shared.u64 t, %1; cvt.u32.u64 %0, t; }" : "=r"(a) : "l"(p));
    return a;
}
__device__ __forceinline__ void ldm_x4(uint32_t& r0, uint32_t& r1, uint32_t& r2, uint32_t& r3,
                                       uint32_t addr) {
    asm volatile("ldmatrix.sync.aligned.m8n8.x4.shared.b16 {%0,%1,%2,%3}, [%4];"
                 : "=r"(r0), "=r"(r1), "=r"(r2), "=r"(r3) : "r"(addr));
}
__device__ __forceinline__ void mma_bf16(float* c, const uint32_t* a, const uint32_t* b) {
    asm volatile(
        "mma.sync.aligned.m16n8k16.row.col.f32.bf16.bf16.f32 "
        "{%0,%1,%2,%3},{%4,%5,%6,%7},{%8,%9},{%0,%1,%2,%3};"
        : "+f"(c[0]), "+f"(c[1]), "+f"(c[2]), "+f"(c[3])
        : "r"(a[0]), "r"(a[1]), "r"(a[2]), "r"(a[3]), "r"(b[0]), "r"(b[1]));
}

// ---------------- edge index access (dtype detected at runtime) ----------------
__device__ __forceinline__ int edge_at(const void* ei, long long pos) {
    if (g_is64) return (int)((const long long*)ei)[pos];
    return ((const int*)ei)[pos];
}

// init counters + parallel int64 detection + fused W hi/lo split
__global__ void k_init(const int* ei32, const float* __restrict__ W, int E, int N) {
    int i = blockIdx.x * blockDim.x + threadIdx.x;
    if (blockIdx.x == 0 && threadIdx.x < 32) {
        int lane = threadIdx.x;
        int bad = 0;
        if (lane < E && ei32[2 * lane + 1] != 0) bad = 1;
        int k2 = lane + 32;
        if (k2 < E && k2 < 64 && ei32[2 * k2 + 1] != 0) bad = 1;
        unsigned m = __ballot_sync(0xffffffffu, bad);
        if (lane == 0) g_is64 = (m == 0u);
    }
    if (i < N) g_counts[i] = 0;
    if (i < 2 * D) g_stats[i] = 0.0f;
    if (i < 16384) {
        int r = i >> 7, k = i & 127;
        float w = W[i];
        __nv_bfloat16 hi = __float2bfloat16(w);
        __nv_bfloat16 lo = __float2bfloat16(w - __bfloat162float(hi));
        int kc = k >> 3;
        int idx = (r * 16 + (kc ^ (r & 7))) * 8 + (k & 7);
        g_Whi_img[idx] = hi;
        g_Wlo_img[idx] = lo;
    }
}

__global__ void k_hist(const void* ei, int E) {
    int e = blockIdx.x * blockDim.x + threadIdx.x;
    if (e >= E) return;
    int d = edge_at(ei, (long long)E + e);
    atomicAdd(&g_counts[d], 1);
}

// ---- scan over g_counts -> g_rowstart ----
__global__ void k_scan1(int N) {
    __shared__ int warp_off[32];
    int t = threadIdx.x;
    int gid = blockIdx.x * 1024 + t;
    int v = (gid < N) ? g_counts[gid] : 0;
    int lane = t & 31, wid = t >> 5;
    int s = v;
#pragma unroll
    for (int off = 1; off < 32; off <<= 1) {
        int n2 = __shfl_up_sync(0xffffffffu, s, off);
        if (lane >= off) s += n2;
    }
    if (lane == 31) warp_off[wid] = s;
    __syncthreads();
    if (wid == 0) {
        int ws = warp_off[lane];
        int ss = ws;
#pragma unroll
        for (int off = 1; off < 32; off <<= 1) {
            int n2 = __shfl_up_sync(0xffffffffu, ss, off);
            if (lane >= off) ss += n2;
        }
        warp_off[lane] = ss - ws;
        if (lane == 31) g_blocksums[blockIdx.x] = ss;
    }
    __syncthreads();
    if (gid < N) g_rowstart[gid] = s + warp_off[wid] - v;
}

// scan3: grid 1:1 with scan1 blocks (1024 threads); warp 0 computes the prefix once.
__global__ __launch_bounds__(1024) void k_scan3(int N) {
    __shared__ int s_off;
    int t = threadIdx.x;
    int b = blockIdx.x;
    if (t < 32) {
        int acc = 0;
#pragma unroll
        for (int j = 0; j < 4; j++) {
            int idx = t + j * 32;
            if (idx < b) acc += g_blocksums[idx];
        }
#pragma unroll
        for (int off = 16; off > 0; off >>= 1)
            acc += __shfl_down_sync(0xffffffffu, acc, off);
        if (t == 0) s_off = acc;
    }
    __syncthreads();
    int i = blockIdx.x * 1024 + t;
    if (i >= N) return;
    int rs = g_rowstart[i] + s_off;
    g_rowstart[i] = rs;
    g_cursor[i]   = rs;
    g_dinv[i]     = rsqrtf((float)g_counts[i] + 1.0f);
}

__global__ void k_fill(const void* ei, int E) {
    int e = blockIdx.x * blockDim.x + threadIdx.x;
    if (e >= E) return;
    int s = edge_at(ei, e);
    int d = edge_at(ei, (long long)E + e);
    int pos = atomicAdd(&g_cursor[d], 1);
    if (pos < EMAX) g_csr[pos] = s;
}

// ------ GEMM: h' = dinv * (x @ W^T) -> fp16, 64-row tiles, 2 CTAs/SM -------------
#define SM_AHI 0
#define SM_ALO 16384
#define SM_BHI 32768
#define SM_BLO 65536
#define SM_TOT 98304

__global__ __launch_bounds__(256) void k_gemm_mma(const float* __restrict__ x, int N) {
    extern __shared__ char smem[];
    uint32_t sb = smem_u32(smem);
    int tid = threadIdx.x;
    int row0 = blockIdx.x * 64;

    // ---- copy pre-swizzled W hi/lo images (2048 uint4 each) ----
    {
        const uint4* wh = (const uint4*)g_Whi_img;
        const uint4* wl = (const uint4*)g_Wlo_img;
        uint4* bh = (uint4*)(smem + SM_BHI);
        uint4* bl = (uint4*)(smem + SM_BLO);
        for (int i = tid; i < 2048; i += 256) { bh[i] = wh[i]; bl[i] = wl[i]; }
    }

    // ---- convert this tile's 64 x rows to bf16 hi/lo, swizzled ----
    {
        int r = tid >> 2;
        int q = tid & 3;
        int gr = row0 + r;
        char* Ah = smem + SM_AHI;
        char* Al = smem + SM_ALO;
        if (gr < N) {
            const float4* xr = (const float4*)(x + (size_t)gr * 128) + q * 8;
#pragma unroll
            for (int j = 0; j < 4; j++) {
                float4 v0 = xr[2 * j];
                float4 v1 = xr[2 * j + 1];
                float f[8] = {v0.x, v0.y, v0.z, v0.w, v1.x, v1.y, v1.z, v1.w};
                uint32_t hw[4], lw[4];
#pragma unroll
                for (int p = 0; p < 4; p++) {
                    float a = f[2 * p], b = f[2 * p + 1];
                    __nv_bfloat16 ha = __float2bfloat16(a);
                    __nv_bfloat16 hb = __float2bfloat16(b);
                    union { __nv_bfloat162 v; uint32_t u; } ch, cl;
                    ch.v = __nv_bfloat162(ha, hb);
                    cl.v = __nv_bfloat162(__float2bfloat16(a - __bfloat162float(ha)),
                                          __float2bfloat16(b - __bfloat162float(hb)));
                    hw[p] = ch.u;
                    lw[p] = cl.u;
                }
                int kc = q * 4 + j;
                int off = (r * 16 + (kc ^ (r & 7))) * 16;
                *(uint4*)(Ah + off) = make_uint4(hw[0], hw[1], hw[2], hw[3]);
                *(uint4*)(Al + off) = make_uint4(lw[0], lw[1], lw[2], lw[3]);
            }
        } else {
            uint4 z = make_uint4(0, 0, 0, 0);
#pragma unroll
            for (int j = 0; j < 4; j++) {
                int kc = q * 4 + j;
                int off = (r * 16 + (kc ^ (r & 7))) * 16;
                *(uint4*)(smem + SM_AHI + off) = z;
                *(uint4*)(smem + SM_ALO + off) = z;
            }
        }
    }
    __syncthreads();

    // ---- 8 warps: 2(m) x 4(n) -> warp tile 32(m) x 32(n) ----
    int warp = tid >> 5, lane = tid & 31;
    int wm = warp & 1, wn = warp >> 1;
    int m0 = wm * 32, n0 = wn * 32;
    int sub = lane >> 3, lrow = lane & 7;

    float acc[2][4][4];
#pragma unroll
    for (int mt = 0; mt < 2; mt++)
#pragma unroll
        for (int nt = 0; nt < 4; nt++)
#pragma unroll
            for (int q = 0; q < 4; q++) acc[mt][nt][q] = 0.f;

    int a_row_off = ((sub & 1) << 3) + lrow;
    int a_halfk   = sub >> 1;
    int b_row_off = ((sub & 2) << 2) + lrow;
    int b_halfk   = sub & 1;

#pragma unroll
    for (int ks = 0; ks < 8; ks++) {
        uint32_t ah[2][4], al[2][4], bh[4][2], bl[4][2];
#pragma unroll
        for (int mt = 0; mt < 2; mt++) {
            int r = m0 + mt * 16 + a_row_off;
            int kc = 2 * ks + a_halfk;
            uint32_t addr = (uint32_t)((r * 16 + (kc ^ (r & 7))) * 16);
            ldm_x4(ah[mt][0], ah[mt][1], ah[mt][2], ah[mt][3], sb + SM_AHI + addr);
            ldm_x4(al[mt][0], al[mt][1], al[mt][2], al[mt][3], sb + SM_ALO + addr);
        }
#pragma unroll
        for (int np = 0; np < 2; np++) {
            int r = n0 + np * 16 + b_row_off;
            int kc = 2 * ks + b_halfk;
            uint32_t addr = (uint32_t)((r * 16 + (kc ^ (r & 7))) * 16);
            ldm_x4(bh[2 * np][0], bh[2 * np][1], bh[2 * np + 1][0], bh[2 * np + 1][1],
                   sb + SM_BHI + addr);
            ldm_x4(bl[2 * np][0], bl[2 * np][1], bl[2 * np + 1][0], bl[2 * np + 1][1],
                   sb + SM_BLO + addr);
        }
#pragma unroll
        for (int mt = 0; mt < 2; mt++)
#pragma unroll
            for (int nt = 0; nt < 4; nt++) {
                mma_bf16(acc[mt][nt], ah[mt], bh[nt]);
                mma_bf16(acc[mt][nt], ah[mt], bl[nt]);
                mma_bf16(acc[mt][nt], al[mt], bh[nt]);
            }
    }

    // ---- epilogue: prescale rows by dinv, fp16 stores (half2 per 2 cols) ----
    int qrow = lane >> 2, qcol = (lane & 3) * 2;
    __half2* h2 = (__half2*)g_hh;
#pragma unroll
    for (int mt = 0; mt < 2; mt++) {
        int r_lo = row0 + m0 + mt * 16 + qrow;
        int r_hi = r_lo + 8;
        float d_lo = (r_lo < N) ? g_dinv[r_lo] : 0.f;
        float d_hi = (r_hi < N) ? g_dinv[r_hi] : 0.f;
#pragma unroll
        for (int nt = 0; nt < 4; nt++) {
            int col = n0 + nt * 8 + qcol;
            if (r_lo < N)
                h2[(size_t)r_lo * 64 + (col >> 1)] =
                    __floats2half2_rn(d_lo * acc[mt][nt][0], d_lo * acc[mt][nt][1]);
            if (r_hi < N)
                h2[(size_t)r_hi * 64 + (col >> 1)] =
                    __floats2half2_rn(d_hi * acc[mt][nt][2], d_hi * acc[mt][nt][3]);
        }
    }
}

// ------- aggregation (grid-stride, warp per node) + fused BN statistics ----------
// out[dst] = dinv[dst] * (sum_{src in nbrs} h'[src] + h'[dst]) + b   (h' in fp16)
__global__ __launch_bounds__(256) void k_agg(const float* __restrict__ bias,
                                             float* __restrict__ out, int N, int totalWarps) {
    __shared__ float sh_sum[128];
    __shared__ float sh_sq[128];
    int tid = threadIdx.x;
    int lane = tid & 31;
    if (tid < 128) { sh_sum[tid] = 0.f; sh_sq[tid] = 0.f; }
    __syncthreads();

    int gwarp = blockIdx.x * 8 + (tid >> 5);
    const uint2* hrow = (const uint2*)g_hh;   // 16 uint2 per row? no: 128 half = 32 uint2
    float4 bb = ((const float4*)bias)[lane];
    float4 ssum = make_float4(0.f, 0.f, 0.f, 0.f);
    float4 ssq  = make_float4(0.f, 0.f, 0.f, 0.f);

    for (int node = gwarp; node < N; node += totalWarps) {
        int   base = g_rowstart[node];
        int   cnt  = g_counts[node];
        float di   = g_dinv[node];

        // self term
        float4 a0, a1, a2, a3;
        {
            uint2 v = hrow[(size_t)node * 32 + lane];
            float2 p0 = __half22float2(*(__half2*)&v.x);
            float2 p1 = __half22float2(*(__half2*)&v.y);
            a0 = make_float4(p0.x, p0.y, p1.x, p1.y);
        }
        a1 = make_float4(0.f, 0.f, 0.f, 0.f);
        a2 = make_float4(0.f, 0.f, 0.f, 0.f);
        a3 = make_float4(0.f, 0.f, 0.f, 0.f);

        for (int j0 = 0; j0 < cnt; j0 += 32) {
            int myj = j0 + lane;
            int s = (myj < cnt) ? g_csr[base + myj] : 0;
            int m = min(32, cnt - j0);
            int t = 0;
            for (; t + 4 <= m; t += 4) {
                int sv0 = __shfl_sync(0xffffffffu, s, t);
                int sv1 = __shfl_sync(0xffffffffu, s, t + 1);
                int sv2 = __shfl_sync(0xffffffffu, s, t + 2);
                int sv3 = __shfl_sync(0xffffffffu, s, t + 3);
                uint2 v0 = hrow[(size_t)sv0 * 32 + lane];
                uint2 v1 = hrow[(size_t)sv1 * 32 + lane];
                uint2 v2 = hrow[(size_t)sv2 * 32 + lane];
                uint2 v3 = hrow[(size_t)sv3 * 32 + lane];
                float2 q0, q1;
                q0 = __half22float2(*(__half2*)&v0.x); q1 = __half22float2(*(__half2*)&v0.y);
                a0.x += q0.x; a0.y += q0.y; a0.z += q1.x; a0.w += q1.y;
                q0 = __half22float2(*(__half2*)&v1.x); q1 = __half22float2(*(__half2*)&v1.y);
                a1.x += q0.x; a1.y += q0.y; a1.z += q1.x; a1.w += q1.y;
                q0 = __half22float2(*(__half2*)&v2.x); q1 = __half22float2(*(__half2*)&v2.y);
                a2.x += q0.x; a2.y += q0.y; a2.z += q1.x; a2.w += q1.y;
                q0 = __half22float2(*(__half2*)&v3.x); q1 = __half22float2(*(__half2*)&v3.y);
                a3.x += q0.x; a3.y += q0.y; a3.z += q1.x; a3.w += q1.y;
            }
            for (; t < m; t++) {
                int sv0 = __shfl_sync(0xffffffffu, s, t);
                uint2 v0 = hrow[(size_t)sv0 * 32 + lane];
                float2 q0 = __half22float2(*(__half2*)&v0.x);
                float2 q1 = __half22float2(*(__half2*)&v0.y);
                a0.x += q0.x; a0.y += q0.y; a0.z += q1.x; a0.w += q1.y;
            }
        }
        float4 o;
        o.x = di * ((a0.x + a1.x) + (a2.x + a3.x)) + bb.x;
        o.y = di * ((a0.y + a1.y) + (a2.y + a3.y)) + bb.y;
        o.z = di * ((a0.z + a1.z) + (a2.z + a3.z)) + bb.z;
        o.w = di * ((a0.w + a1.w) + (a2.w + a3.w)) + bb.w;
        ((float4*)out)[(size_t)node * 32 + lane] = o;
        ssum.x += o.x; ssum.y += o.y; ssum.z += o.z; ssum.w += o.w;
        ssq.x += o.x * o.x; ssq.y += o.y * o.y; ssq.z += o.z * o.z; ssq.w += o.w * o.w;
    }

    atomicAdd(&sh_sum[lane * 4 + 0], ssum.x);
    atomicAdd(&sh_sum[lane * 4 + 1], ssum.y);
    atomicAdd(&sh_sum[lane * 4 + 2], ssum.z);
    atomicAdd(&sh_sum[lane * 4 + 3], ssum.w);
    atomicAdd(&sh_sq[lane * 4 + 0], ssq.x);
    atomicAdd(&sh_sq[lane * 4 + 1], ssq.y);
    atomicAdd(&sh_sq[lane * 4 + 2], ssq.z);
    atomicAdd(&sh_sq[lane * 4 + 3], ssq.w);
    __syncthreads();
    if (tid < 128) {
        atomicAdd(&g_stats[tid], sh_sum[tid]);
        atomicAdd(&g_stats[D + tid], sh_sq[tid]);
    }
}

// ---------------- BN + ReLU + residual -------------------------------------------
__global__ void k_final(const float* __restrict__ x, const float* __restrict__ gamma,
                        const float* __restrict__ beta, float* __restrict__ out, int N) {
    long long i = (long long)blockIdx.x * blockDim.x + threadIdx.x;
    long long total = (long long)N * 32;
    if (i >= total) return;
    int c4 = (int)(i & 31);
    float invN = 1.0f / (float)N;
    float4 v  = ((float4*)out)[i];
    float4 xv = ((const float4*)x)[i];
    float r[4] = {v.x, v.y, v.z, v.w};
    float xr[4] = {xv.x, xv.y, xv.z, xv.w};
#pragma unroll
    for (int c = 0; c < 4; c++) {
        int col = c4 * 4 + c;
        float mu  = g_stats[col] * invN;
        float var = g_stats[D + col] * invN - mu * mu;
        float inv = rsqrtf(var + BN_EPS);
        float y = __ldg(&gamma[col]) * (r[c] - mu) * inv + __ldg(&beta[col]);
        y = fmaxf(y, 0.0f);
        r[c] = y + xr[c];
    }
    ((float4*)out)[i] = make_float4(r[0], r[1], r[2], r[3]);
}

// ---------------- launcher --------------------------------------------------------
extern "C" void kernel_launch(void* const* d_in, const int* in_sizes, int n_in,
                              void* d_out, int out_size) {
    const float* x     = (const float*)d_in[0];
    const float* W     = (const float*)d_in[1];
    const float* bias  = (const float*)d_in[2];
    const float* gamma = (const float*)d_in[3];
    const float* beta  = (const float*)d_in[4];
    const void*  ei    = d_in[5];
    int N = in_sizes[0] / D;
    int E = in_sizes[5] / 2;
    float* out = (float*)d_out;

    cudaFuncSetAttribute(k_gemm_mma, cudaFuncAttributeMaxDynamicSharedMemorySize, SM_TOT);

    k_init<<<(N + 255) / 256, 256>>>((const int*)ei, W, E, N);
    k_hist<<<(E + 255) / 256, 256>>>(ei, E);
    int nblk = (N + 1023) / 1024;
    k_scan1<<<nblk, 1024>>>(N);
    k_scan3<<<nblk, 1024>>>(N);
    k_fill<<<(E + 255) / 256, 256>>>(ei, E);
    k_gemm_mma<<<(N + 63) / 64, 256, SM_TOT>>>(x, N);
    int aggBlocks = 1036;                       // 7 blocks/SM * 148
    k_agg<<<aggBlocks, 256>>>(bias, out, N, aggBlocks * 8);
    k_final<<<(int)(((long long)N * 32 + 255) / 256), 256>>>(x, gamma, beta, out, N);
}